// round 1
// baseline (speedup 1.0000x reference)
#include <cuda_runtime.h>
#include <math.h>

#define NB   64   // batch
#define NHP  64   // heads-planes (seq axis)
#define NH_  64   // H
#define NW_  64   // W
#define ND   32   // D
#define NDFF 64
#define PIX  (NH_*NW_)        // 4096 per (b,hp)
#define NP   (NB*NHP)         // 4096 pairs

// scratch: feat [B, HP, D]
__device__ float g_feat[NP * ND];

// ---------------------------------------------------------------------------
// Kernel 1: per-(b,hp) stats over 4096 elements + in_proj -> g_feat
// ---------------------------------------------------------------------------
__global__ __launch_bounds__(256) void stats_kernel(
    const float* __restrict__ a, const float* __restrict__ b,
    const float* __restrict__ layer_emb,
    const float* __restrict__ in_proj_w,   // [D,12]
    const float* __restrict__ in_proj_b)   // [D]
{
    const int p   = blockIdx.x;
    const int tid = threadIdx.x;
    const float4* a4 = (const float4*)(a + (size_t)p * PIX);
    const float4* b4 = (const float4*)(b + (size_t)p * PIX);

    float sa = 0.f, sa2 = 0.f, sb = 0.f, sb2 = 0.f, dt = 0.f;
    float mna =  3.4e38f, mxa = -3.4e38f;
    float mnb =  3.4e38f, mxb = -3.4e38f;

#pragma unroll
    for (int k = 0; k < 4; k++) {
        float4 x = __ldg(&a4[tid + k * 256]);
        float4 y = __ldg(&b4[tid + k * 256]);
#define ACC(u, v)                                                   \
        { float _u = (u), _v = (v);                                  \
          sa += _u; sa2 += _u * _u; sb += _v; sb2 += _v * _v;        \
          dt += _u * _v;                                             \
          mna = fminf(mna, _u); mxa = fmaxf(mxa, _u);                \
          mnb = fminf(mnb, _v); mxb = fmaxf(mxb, _v); }
        ACC(x.x, y.x); ACC(x.y, y.y); ACC(x.z, y.z); ACC(x.w, y.w);
#undef ACC
    }

    // warp reduce 9 values
#pragma unroll
    for (int o = 16; o; o >>= 1) {
        sa  += __shfl_down_sync(0xffffffffu, sa,  o);
        sa2 += __shfl_down_sync(0xffffffffu, sa2, o);
        sb  += __shfl_down_sync(0xffffffffu, sb,  o);
        sb2 += __shfl_down_sync(0xffffffffu, sb2, o);
        dt  += __shfl_down_sync(0xffffffffu, dt,  o);
        mna = fminf(mna, __shfl_down_sync(0xffffffffu, mna, o));
        mxa = fmaxf(mxa, __shfl_down_sync(0xffffffffu, mxa, o));
        mnb = fminf(mnb, __shfl_down_sync(0xffffffffu, mnb, o));
        mxb = fmaxf(mxb, __shfl_down_sync(0xffffffffu, mxb, o));
    }

    __shared__ float red[8][9];
    __shared__ float stats[12];
    const int w = tid >> 5, l = tid & 31;
    if (l == 0) {
        red[w][0] = sa;  red[w][1] = sa2; red[w][2] = sb;  red[w][3] = sb2;
        red[w][4] = dt;  red[w][5] = mna; red[w][6] = mxa; red[w][7] = mnb;
        red[w][8] = mxb;
    }
    __syncthreads();

    if (tid == 0) {
        float SA = red[0][0], SA2 = red[0][1], SB = red[0][2], SB2 = red[0][3];
        float DT = red[0][4], MNA = red[0][5], MXA = red[0][6];
        float MNB = red[0][7], MXB = red[0][8];
#pragma unroll
        for (int i = 1; i < 8; i++) {
            SA += red[i][0]; SA2 += red[i][1]; SB += red[i][2]; SB2 += red[i][3];
            DT += red[i][4];
            MNA = fminf(MNA, red[i][5]); MXA = fmaxf(MXA, red[i][6]);
            MNB = fminf(MNB, red[i][7]); MXB = fmaxf(MXB, red[i][8]);
        }
        const float n = (float)PIX;
        const float invn = 1.f / n, invn1 = 1.f / (n - 1.f);
        float mean_a = SA * invn;
        float std_a  = sqrtf(fmaxf((SA2 - SA * SA * invn) * invn1, 0.f));
        float mean_b = SB * invn;
        float std_b  = sqrtf(fmaxf((SB2 - SB * SB * invn) * invn1, 0.f));
        float na = sqrtf(SA2), nb = sqrtf(SB2);
        float cosv = DT / (fmaxf(na, 1e-8f) * fmaxf(nb, 1e-8f));
        float SD  = SA - SB;
        float SD2 = SA2 + SB2 - 2.f * DT;
        float mean_d = SD * invn;
        float std_d  = sqrtf(fmaxf((SD2 - SD * SD * invn) * invn1, 0.f));
        float norm_d = sqrtf(fmaxf(SD2, 0.f));
        stats[0] = mean_a; stats[1] = std_a; stats[2] = MNA;  stats[3] = MXA;
        stats[4] = mean_b; stats[5] = std_b; stats[6] = MNB;  stats[7] = MXB;
        stats[8] = mean_d; stats[9] = std_d; stats[10] = norm_d; stats[11] = cosv;
    }
    __syncthreads();

    if (tid < ND) {
        float s = __ldg(&in_proj_b[tid]) + __ldg(&layer_emb[tid]);
#pragma unroll
        for (int j = 0; j < 12; j++)
            s += stats[j] * __ldg(&in_proj_w[tid * 12 + j]);
        g_feat[(size_t)p * ND + tid] = s;
    }
}

// ---------------------------------------------------------------------------
// Kernel 2: per-batch tiny transformer over HP=64 tokens, D=32 (in place)
// ---------------------------------------------------------------------------
__global__ __launch_bounds__(256) void xform_kernel(
    const float* __restrict__ ln1_g, const float* __restrict__ ln1_b,
    const float* __restrict__ qkv_w, const float* __restrict__ qkv_b,  // [96,32],[96]
    const float* __restrict__ out_w, const float* __restrict__ out_b,  // [32,32],[32]
    const float* __restrict__ ln2_g, const float* __restrict__ ln2_b,
    const float* __restrict__ w1,    const float* __restrict__ b1,     // [64,32],[64]
    const float* __restrict__ w2,    const float* __restrict__ b2)     // [32,64],[32]
{
    __shared__ float sfeat[NHP][ND];   // running residual stream
    __shared__ float sx[NHP][ND];      // LN out / attn out
    __shared__ float sqkv[NHP][96];    // qkv, reused for FFN hidden

    const int bb  = blockIdx.x;
    const int tid = threadIdx.x;
    float* gf = g_feat + (size_t)bb * NHP * ND;

    for (int i = tid; i < NHP * ND; i += 256) ((float*)sfeat)[i] = gf[i];
    __syncthreads();

    // ---- LN1 ----
    if (tid < NHP) {
        float m = 0.f;
#pragma unroll
        for (int d = 0; d < ND; d++) m += sfeat[tid][d];
        m *= (1.f / ND);
        float v = 0.f;
#pragma unroll
        for (int d = 0; d < ND; d++) { float t = sfeat[tid][d] - m; v += t * t; }
        float r = rsqrtf(v * (1.f / ND) + 1e-5f);
#pragma unroll
        for (int d = 0; d < ND; d++)
            sx[tid][d] = (sfeat[tid][d] - m) * r * __ldg(&ln1_g[d]) + __ldg(&ln1_b[d]);
    }
    __syncthreads();

    // ---- QKV: 64*96 outputs ----
    for (int i = tid; i < NHP * 96; i += 256) {
        int t = i / 96, j = i % 96;
        float s = __ldg(&qkv_b[j]);
        const float* wr = qkv_w + j * ND;
#pragma unroll
        for (int k = 0; k < ND; k++) s += sx[t][k] * __ldg(&wr[k]);
        sqkv[t][j] = s;
    }
    __syncthreads();

    // ---- Attention: thread = (query token, head); online softmax (2 passes) ----
    if (tid < 128) {
        int qt = tid >> 1, h = tid & 1;
        float qv[16];
#pragma unroll
        for (int d = 0; d < 16; d++) qv[d] = sqkv[qt][h * 16 + d];
        float mx = -3.4e38f;
        for (int kk = 0; kk < NHP; kk++) {
            float s = 0.f;
#pragma unroll
            for (int d = 0; d < 16; d++) s += qv[d] * sqkv[kk][32 + h * 16 + d];
            mx = fmaxf(mx, s * 0.25f);
        }
        float den = 0.f;
        float acc[16];
#pragma unroll
        for (int d = 0; d < 16; d++) acc[d] = 0.f;
        for (int kk = 0; kk < NHP; kk++) {
            float s = 0.f;
#pragma unroll
            for (int d = 0; d < 16; d++) s += qv[d] * sqkv[kk][32 + h * 16 + d];
            float e = expf(s * 0.25f - mx);
            den += e;
#pragma unroll
            for (int d = 0; d < 16; d++) acc[d] += e * sqkv[kk][64 + h * 16 + d];
        }
        float inv = 1.f / den;
#pragma unroll
        for (int d = 0; d < 16; d++) sx[qt][h * 16 + d] = acc[d] * inv;
    }
    __syncthreads();

    // ---- out proj + residual ----
    for (int i = tid; i < NHP * ND; i += 256) {
        int t = i / ND, d = i % ND;
        float s = __ldg(&out_b[d]);
        const float* wr = out_w + d * ND;
#pragma unroll
        for (int k = 0; k < ND; k++) s += sx[t][k] * __ldg(&wr[k]);
        sfeat[t][d] += s;
    }
    __syncthreads();

    // ---- LN2 ----
    if (tid < NHP) {
        float m = 0.f;
#pragma unroll
        for (int d = 0; d < ND; d++) m += sfeat[tid][d];
        m *= (1.f / ND);
        float v = 0.f;
#pragma unroll
        for (int d = 0; d < ND; d++) { float t = sfeat[tid][d] - m; v += t * t; }
        float r = rsqrtf(v * (1.f / ND) + 1e-5f);
#pragma unroll
        for (int d = 0; d < ND; d++)
            sx[tid][d] = (sfeat[tid][d] - m) * r * __ldg(&ln2_g[d]) + __ldg(&ln2_b[d]);
    }
    __syncthreads();

    // ---- FFN1 + exact GELU (into sqkv) ----
    for (int i = tid; i < NHP * NDFF; i += 256) {
        int t = i / NDFF, j = i % NDFF;
        float s = __ldg(&b1[j]);
        const float* wr = w1 + j * ND;
#pragma unroll
        for (int k = 0; k < ND; k++) s += sx[t][k] * __ldg(&wr[k]);
        sqkv[t][j] = 0.5f * s * (1.f + erff(s * 0.70710678118654752f));
    }
    __syncthreads();

    // ---- FFN2 + residual ----
    for (int i = tid; i < NHP * ND; i += 256) {
        int t = i / ND, d = i % ND;
        float s = __ldg(&b2[d]);
        const float* wr = w2 + d * NDFF;
#pragma unroll
        for (int k = 0; k < NDFF; k++) s += sqkv[t][k] * __ldg(&wr[k]);
        sfeat[t][d] += s;
    }
    __syncthreads();

    for (int i = tid; i < NHP * ND; i += 256) gf[i] = ((float*)sfeat)[i];
}

// ---------------------------------------------------------------------------
// Kernel 3: heads + merge (the big memory pass)
// ---------------------------------------------------------------------------
__global__ __launch_bounds__(256) void merge_kernel(
    const float* __restrict__ a, const float* __restrict__ b,
    const float* __restrict__ gate_w, const float* __restrict__ gate_b, // [1,32],[1]
    const float* __restrict__ row_w,  const float* __restrict__ row_b,  // [64,32],[64]
    const float* __restrict__ col_w,  const float* __restrict__ col_b,
    const float* __restrict__ drow_w, const float* __restrict__ drow_b,
    const float* __restrict__ dcol_w, const float* __restrict__ dcol_b,
    const float* __restrict__ delta_scale,
    float* __restrict__ out)
{
    __shared__ float f[ND];
    __shared__ float rowg[NH_];   // gate + row[h]
    __shared__ float colv[NW_];
    __shared__ float drv[NH_];    // delta_scale * d_row[h]
    __shared__ float dcv[NW_];

    const int p   = blockIdx.x;
    const int tid = threadIdx.x;
    if (tid < ND) f[tid] = g_feat[(size_t)p * ND + tid];
    __syncthreads();

    {
        // every thread computes gate (cheap, avoids an extra sync)
        float gate = __ldg(&gate_b[0]);
#pragma unroll
        for (int k = 0; k < ND; k++) gate += f[k] * __ldg(&gate_w[k]);

        const int j   = tid & 63;
        const int grp = tid >> 6;
        if (grp == 0) {
            float s = __ldg(&row_b[j]);
            const float* wr = row_w + j * ND;
#pragma unroll
            for (int k = 0; k < ND; k++) s += f[k] * __ldg(&wr[k]);
            rowg[j] = gate + s;
        } else if (grp == 1) {
            float s = __ldg(&col_b[j]);
            const float* wr = col_w + j * ND;
#pragma unroll
            for (int k = 0; k < ND; k++) s += f[k] * __ldg(&wr[k]);
            colv[j] = s;
        } else if (grp == 2) {
            float ds = __ldg(&delta_scale[0]);
            float s = __ldg(&drow_b[j]);
            const float* wr = drow_w + j * ND;
#pragma unroll
            for (int k = 0; k < ND; k++) s += f[k] * __ldg(&wr[k]);
            drv[j] = s * ds;
        } else {
            float s = __ldg(&dcol_b[j]);
            const float* wr = dcol_w + j * ND;
#pragma unroll
            for (int k = 0; k < ND; k++) s += f[k] * __ldg(&wr[k]);
            dcv[j] = s;
        }
    }
    __syncthreads();

    const float4* a4 = (const float4*)(a + (size_t)p * PIX);
    const float4* b4 = (const float4*)(b + (size_t)p * PIX);
    float4*       o4 = (float4*)out + (size_t)p * (PIX / 4);

#pragma unroll
    for (int it = 0; it < 4; it++) {
        int i4 = tid + it * 256;
        int h  = i4 >> 4;           // 16 float4 per row of 64
        int w0 = (i4 & 15) << 2;
        float4 av = __ldg(&a4[i4]);
        float4 bv = __ldg(&b4[i4]);
        float rg = rowg[h];
        float dr = drv[h];
        float4 ov;
#define MERGE1(comp, wi)                                                  \
        { float l = rg + colv[wi];                                         \
          float m = 1.f / (1.f + expf(-l));                                \
          ov.comp = bv.comp + m * (av.comp - bv.comp) + dr * dcv[wi]; }
        MERGE1(x, w0 + 0); MERGE1(y, w0 + 1); MERGE1(z, w0 + 2); MERGE1(w, w0 + 3);
#undef MERGE1
        o4[i4] = ov;
    }
}

// ---------------------------------------------------------------------------
extern "C" void kernel_launch(void* const* d_in, const int* in_sizes, int n_in,
                              void* d_out, int out_size)
{
    const float* a          = (const float*)d_in[0];
    const float* b          = (const float*)d_in[1];
    const float* layer_emb  = (const float*)d_in[2];
    const float* in_proj_w  = (const float*)d_in[3];
    const float* in_proj_b  = (const float*)d_in[4];
    const float* ln1_g      = (const float*)d_in[5];
    const float* ln1_b      = (const float*)d_in[6];
    const float* qkv_w      = (const float*)d_in[7];
    const float* qkv_b      = (const float*)d_in[8];
    const float* out_w      = (const float*)d_in[9];
    const float* out_b      = (const float*)d_in[10];
    const float* ln2_g      = (const float*)d_in[11];
    const float* ln2_b      = (const float*)d_in[12];
    const float* ffn_w1     = (const float*)d_in[13];
    const float* ffn_b1     = (const float*)d_in[14];
    const float* ffn_w2     = (const float*)d_in[15];
    const float* ffn_b2     = (const float*)d_in[16];
    const float* gate_w     = (const float*)d_in[17];
    const float* gate_b     = (const float*)d_in[18];
    const float* row_w      = (const float*)d_in[19];
    const float* row_b      = (const float*)d_in[20];
    const float* col_w      = (const float*)d_in[21];
    const float* col_b      = (const float*)d_in[22];
    const float* drow_w     = (const float*)d_in[23];
    const float* drow_b     = (const float*)d_in[24];
    const float* dcol_w     = (const float*)d_in[25];
    const float* dcol_b     = (const float*)d_in[26];
    const float* dscale     = (const float*)d_in[27];
    float* out              = (float*)d_out;

    stats_kernel<<<NP, 256>>>(a, b, layer_emb, in_proj_w, in_proj_b);
    xform_kernel<<<NB, 256>>>(ln1_g, ln1_b, qkv_w, qkv_b, out_w, out_b,
                              ln2_g, ln2_b, ffn_w1, ffn_b1, ffn_w2, ffn_b2);
    merge_kernel<<<NP, 256>>>(a, b, gate_w, gate_b, row_w, row_b,
                              col_w, col_b, drow_w, drow_b, dcol_w, dcol_b,
                              dscale, out);
}

// round 2
// speedup vs baseline: 1.0011x; 1.0011x over previous
#include <cuda_runtime.h>
#include <math.h>

#define NB   64
#define NHP  64
#define NH_  64
#define NW_  64
#define ND   32
#define NDFF 64
#define PIX  (NH_*NW_)
#define NP   (NB*NHP)
#define THREADS 256

// scratch: feat [B, HP, D]
__device__ float g_feat[NP * ND];
// monotone barrier tickets (never reset; replay-safe)
__device__ unsigned int g_bar[2];

__device__ __forceinline__ void grid_barrier(unsigned int* ctr, unsigned int nblocks)
{
    __syncthreads();
    if (threadIdx.x == 0) {
        __threadfence();
        unsigned int t = atomicAdd(ctr, 1u) + 1u;
        // my cohort is complete when ctr reaches the next multiple of nblocks >= t
        unsigned int target = ((t + nblocks - 1u) / nblocks) * nblocks;
        unsigned int v;
        for (;;) {
            asm volatile("ld.acquire.gpu.global.u32 %0, [%1];"
                         : "=r"(v) : "l"(ctr) : "memory");
            if (v >= target) break;
            __nanosleep(64);
        }
        __threadfence();
    }
    __syncthreads();
}

__global__ __launch_bounds__(THREADS) void fused_kernel(
    const float* __restrict__ a, const float* __restrict__ b,
    const float* __restrict__ layer_emb,
    const float* __restrict__ in_proj_w, const float* __restrict__ in_proj_b,
    const float* __restrict__ ln1_g, const float* __restrict__ ln1_b,
    const float* __restrict__ qkv_w, const float* __restrict__ qkv_b,
    const float* __restrict__ out_w, const float* __restrict__ out_b,
    const float* __restrict__ ln2_g, const float* __restrict__ ln2_b,
    const float* __restrict__ w1,    const float* __restrict__ b1,
    const float* __restrict__ w2,    const float* __restrict__ b2,
    const float* __restrict__ gate_w, const float* __restrict__ gate_b,
    const float* __restrict__ row_w,  const float* __restrict__ row_b,
    const float* __restrict__ col_w,  const float* __restrict__ col_b,
    const float* __restrict__ drow_w, const float* __restrict__ drow_b,
    const float* __restrict__ dcol_w, const float* __restrict__ dcol_b,
    const float* __restrict__ delta_scale,
    float* __restrict__ out,
    int nblocks)
{
    __shared__ float sfeat[NHP][ND];   // 8 KB
    __shared__ float sx[NHP][ND];      // 8 KB (also scratch for stats/merge)
    __shared__ float sqkv[NHP][96];    // 24 KB

    const int tid = threadIdx.x;

    // ======================= PHASE 1: stats + in_proj =======================
    {
        float* red   = &sx[0][0];       // [8][9]
        float* stats = &sx[0][0] + 80;  // [12]
        for (int p = blockIdx.x; p < NP; p += nblocks) {
            const float4* a4 = (const float4*)(a + (size_t)p * PIX);
            const float4* b4 = (const float4*)(b + (size_t)p * PIX);

            // front-batched loads (MLP = 8)
            float4 av0 = __ldg(&a4[tid]),       av1 = __ldg(&a4[tid + 256]);
            float4 av2 = __ldg(&a4[tid + 512]), av3 = __ldg(&a4[tid + 768]);
            float4 bv0 = __ldg(&b4[tid]),       bv1 = __ldg(&b4[tid + 256]);
            float4 bv2 = __ldg(&b4[tid + 512]), bv3 = __ldg(&b4[tid + 768]);

            float sa = 0.f, sa2 = 0.f, sb = 0.f, sb2 = 0.f, dt = 0.f;
            float mna =  3.4e38f, mxa = -3.4e38f;
            float mnb =  3.4e38f, mxb = -3.4e38f;
#define ACC(u, v)                                                   \
            { float _u = (u), _v = (v);                              \
              sa += _u; sa2 += _u * _u; sb += _v; sb2 += _v * _v;    \
              dt += _u * _v;                                         \
              mna = fminf(mna, _u); mxa = fmaxf(mxa, _u);            \
              mnb = fminf(mnb, _v); mxb = fmaxf(mxb, _v); }
            ACC(av0.x, bv0.x); ACC(av0.y, bv0.y); ACC(av0.z, bv0.z); ACC(av0.w, bv0.w);
            ACC(av1.x, bv1.x); ACC(av1.y, bv1.y); ACC(av1.z, bv1.z); ACC(av1.w, bv1.w);
            ACC(av2.x, bv2.x); ACC(av2.y, bv2.y); ACC(av2.z, bv2.z); ACC(av2.w, bv2.w);
            ACC(av3.x, bv3.x); ACC(av3.y, bv3.y); ACC(av3.z, bv3.z); ACC(av3.w, bv3.w);
#undef ACC
#pragma unroll
            for (int o = 16; o; o >>= 1) {
                sa  += __shfl_down_sync(0xffffffffu, sa,  o);
                sa2 += __shfl_down_sync(0xffffffffu, sa2, o);
                sb  += __shfl_down_sync(0xffffffffu, sb,  o);
                sb2 += __shfl_down_sync(0xffffffffu, sb2, o);
                dt  += __shfl_down_sync(0xffffffffu, dt,  o);
                mna = fminf(mna, __shfl_down_sync(0xffffffffu, mna, o));
                mxa = fmaxf(mxa, __shfl_down_sync(0xffffffffu, mxa, o));
                mnb = fminf(mnb, __shfl_down_sync(0xffffffffu, mnb, o));
                mxb = fmaxf(mxb, __shfl_down_sync(0xffffffffu, mxb, o));
            }
            const int w = tid >> 5, l = tid & 31;
            if (l == 0) {
                red[w * 9 + 0] = sa;  red[w * 9 + 1] = sa2; red[w * 9 + 2] = sb;
                red[w * 9 + 3] = sb2; red[w * 9 + 4] = dt;  red[w * 9 + 5] = mna;
                red[w * 9 + 6] = mxa; red[w * 9 + 7] = mnb; red[w * 9 + 8] = mxb;
            }
            __syncthreads();
            if (tid == 0) {
                float SA = red[0], SA2 = red[1], SB = red[2], SB2 = red[3];
                float DT = red[4], MNA = red[5], MXA = red[6], MNB = red[7], MXB = red[8];
#pragma unroll
                for (int i = 1; i < 8; i++) {
                    SA += red[i * 9 + 0]; SA2 += red[i * 9 + 1];
                    SB += red[i * 9 + 2]; SB2 += red[i * 9 + 3];
                    DT += red[i * 9 + 4];
                    MNA = fminf(MNA, red[i * 9 + 5]); MXA = fmaxf(MXA, red[i * 9 + 6]);
                    MNB = fminf(MNB, red[i * 9 + 7]); MXB = fmaxf(MXB, red[i * 9 + 8]);
                }
                const float n = (float)PIX;
                const float invn = 1.f / n, invn1 = 1.f / (n - 1.f);
                float mean_a = SA * invn;
                float std_a  = sqrtf(fmaxf((SA2 - SA * SA * invn) * invn1, 0.f));
                float mean_b = SB * invn;
                float std_b  = sqrtf(fmaxf((SB2 - SB * SB * invn) * invn1, 0.f));
                float na = sqrtf(SA2), nb = sqrtf(SB2);
                float cosv = DT / (fmaxf(na, 1e-8f) * fmaxf(nb, 1e-8f));
                float SD  = SA - SB;
                float SD2 = SA2 + SB2 - 2.f * DT;
                float mean_d = SD * invn;
                float std_d  = sqrtf(fmaxf((SD2 - SD * SD * invn) * invn1, 0.f));
                float norm_d = sqrtf(fmaxf(SD2, 0.f));
                stats[0] = mean_a; stats[1] = std_a; stats[2] = MNA;  stats[3] = MXA;
                stats[4] = mean_b; stats[5] = std_b; stats[6] = MNB;  stats[7] = MXB;
                stats[8] = mean_d; stats[9] = std_d; stats[10] = norm_d; stats[11] = cosv;
            }
            __syncthreads();
            if (tid < ND) {
                float s = __ldg(&in_proj_b[tid]) + __ldg(&layer_emb[tid]);
#pragma unroll
                for (int j = 0; j < 12; j++)
                    s += stats[j] * __ldg(&in_proj_w[tid * 12 + j]);
                g_feat[(size_t)p * ND + tid] = s;
            }
        }
    }

    grid_barrier(&g_bar[0], (unsigned)nblocks);

    // ======================= PHASE 2: tiny transformer ======================
    if (blockIdx.x < NB) {
        const int bb = blockIdx.x;
        float* gf = g_feat + (size_t)bb * NHP * ND;

        for (int i = tid; i < NHP * ND; i += THREADS) ((float*)sfeat)[i] = gf[i];
        __syncthreads();

        // LN1
        if (tid < NHP) {
            float m = 0.f;
#pragma unroll
            for (int d = 0; d < ND; d++) m += sfeat[tid][d];
            m *= (1.f / ND);
            float v = 0.f;
#pragma unroll
            for (int d = 0; d < ND; d++) { float t = sfeat[tid][d] - m; v += t * t; }
            float r = rsqrtf(v * (1.f / ND) + 1e-5f);
#pragma unroll
            for (int d = 0; d < ND; d++)
                sx[tid][d] = (sfeat[tid][d] - m) * r * __ldg(&ln1_g[d]) + __ldg(&ln1_b[d]);
        }
        __syncthreads();

        // QKV
        for (int i = tid; i < NHP * 96; i += THREADS) {
            int t = i / 96, j = i % 96;
            float s = __ldg(&qkv_b[j]);
            const float* wr = qkv_w + j * ND;
#pragma unroll
            for (int k = 0; k < ND; k++) s += sx[t][k] * __ldg(&wr[k]);
            sqkv[t][j] = s;
        }
        __syncthreads();

        // attention (thread = query token x head)
        if (tid < 128) {
            int qt = tid >> 1, h = tid & 1;
            float qv[16];
#pragma unroll
            for (int d = 0; d < 16; d++) qv[d] = sqkv[qt][h * 16 + d];
            float mx = -3.4e38f;
            for (int kk = 0; kk < NHP; kk++) {
                float s = 0.f;
#pragma unroll
                for (int d = 0; d < 16; d++) s += qv[d] * sqkv[kk][32 + h * 16 + d];
                mx = fmaxf(mx, s * 0.25f);
            }
            float den = 0.f;
            float acc[16];
#pragma unroll
            for (int d = 0; d < 16; d++) acc[d] = 0.f;
            for (int kk = 0; kk < NHP; kk++) {
                float s = 0.f;
#pragma unroll
                for (int d = 0; d < 16; d++) s += qv[d] * sqkv[kk][32 + h * 16 + d];
                float e = __expf(s * 0.25f - mx);
                den += e;
#pragma unroll
                for (int d = 0; d < 16; d++) acc[d] += e * sqkv[kk][64 + h * 16 + d];
            }
            float inv = __fdividef(1.f, den);
#pragma unroll
            for (int d = 0; d < 16; d++) sx[qt][h * 16 + d] = acc[d] * inv;
        }
        __syncthreads();

        // out proj + residual
        for (int i = tid; i < NHP * ND; i += THREADS) {
            int t = i / ND, d = i % ND;
            float s = __ldg(&out_b[d]);
            const float* wr = out_w + d * ND;
#pragma unroll
            for (int k = 0; k < ND; k++) s += sx[t][k] * __ldg(&wr[k]);
            sfeat[t][d] += s;
        }
        __syncthreads();

        // LN2
        if (tid < NHP) {
            float m = 0.f;
#pragma unroll
            for (int d = 0; d < ND; d++) m += sfeat[tid][d];
            m *= (1.f / ND);
            float v = 0.f;
#pragma unroll
            for (int d = 0; d < ND; d++) { float t = sfeat[tid][d] - m; v += t * t; }
            float r = rsqrtf(v * (1.f / ND) + 1e-5f);
#pragma unroll
            for (int d = 0; d < ND; d++)
                sx[tid][d] = (sfeat[tid][d] - m) * r * __ldg(&ln2_g[d]) + __ldg(&ln2_b[d]);
        }
        __syncthreads();

        // FFN1 + exact GELU
        for (int i = tid; i < NHP * NDFF; i += THREADS) {
            int t = i / NDFF, j = i % NDFF;
            float s = __ldg(&b1[j]);
            const float* wr = w1 + j * ND;
#pragma unroll
            for (int k = 0; k < ND; k++) s += sx[t][k] * __ldg(&wr[k]);
            sqkv[t][j] = 0.5f * s * (1.f + erff(s * 0.70710678118654752f));
        }
        __syncthreads();

        // FFN2 + residual
        for (int i = tid; i < NHP * ND; i += THREADS) {
            int t = i / ND, d = i % ND;
            float s = __ldg(&b2[d]);
            const float* wr = w2 + d * NDFF;
#pragma unroll
            for (int k = 0; k < NDFF; k++) s += sqkv[t][k] * __ldg(&wr[k]);
            sfeat[t][d] += s;
        }
        __syncthreads();

        for (int i = tid; i < NHP * ND; i += THREADS) gf[i] = ((float*)sfeat)[i];
    }

    grid_barrier(&g_bar[1], (unsigned)nblocks);

    // ======================= PHASE 3: heads + merge =========================
    {
        float* f    = &sx[0][0];
        float* rowg = f + 32;
        float* colv = f + 96;
        float* drv  = f + 160;
        float* dcv  = f + 224;

        for (int p = blockIdx.x; p < NP; p += nblocks) {
            __syncthreads();   // guard reuse of shared arrays across pairs
            if (tid < ND) f[tid] = g_feat[(size_t)p * ND + tid];
            __syncthreads();

            {
                float gate = __ldg(&gate_b[0]);
#pragma unroll
                for (int k = 0; k < ND; k++) gate += f[k] * __ldg(&gate_w[k]);

                const int j   = tid & 63;
                const int grp = tid >> 6;
                if (grp == 0) {
                    float s = __ldg(&row_b[j]);
                    const float* wr = row_w + j * ND;
#pragma unroll
                    for (int k = 0; k < ND; k++) s += f[k] * __ldg(&wr[k]);
                    rowg[j] = gate + s;
                } else if (grp == 1) {
                    float s = __ldg(&col_b[j]);
                    const float* wr = col_w + j * ND;
#pragma unroll
                    for (int k = 0; k < ND; k++) s += f[k] * __ldg(&wr[k]);
                    colv[j] = s;
                } else if (grp == 2) {
                    float ds = __ldg(&delta_scale[0]);
                    float s = __ldg(&drow_b[j]);
                    const float* wr = drow_w + j * ND;
#pragma unroll
                    for (int k = 0; k < ND; k++) s += f[k] * __ldg(&wr[k]);
                    drv[j] = s * ds;
                } else {
                    float s = __ldg(&dcol_b[j]);
                    const float* wr = dcol_w + j * ND;
#pragma unroll
                    for (int k = 0; k < ND; k++) s += f[k] * __ldg(&wr[k]);
                    dcv[j] = s;
                }
            }
            __syncthreads();

            const float4* a4 = (const float4*)(a + (size_t)p * PIX);
            const float4* b4 = (const float4*)(b + (size_t)p * PIX);
            float4*       o4 = (float4*)out + (size_t)p * (PIX / 4);

#pragma unroll
            for (int it = 0; it < 4; it++) {
                int i4 = tid + it * 256;
                int h  = i4 >> 4;
                int w0 = (i4 & 15) << 2;
                float4 av = __ldg(&a4[i4]);
                float4 bv = __ldg(&b4[i4]);
                float rg = rowg[h];
                float dr = drv[h];
                float4 ov;
#define MERGE1(comp, wi)                                                   \
                { float lgt = rg + colv[wi];                                \
                  float m = __fdividef(1.f, 1.f + __expf(-lgt));            \
                  ov.comp = bv.comp + m * (av.comp - bv.comp) + dr * dcv[wi]; }
                MERGE1(x, w0 + 0); MERGE1(y, w0 + 1);
                MERGE1(z, w0 + 2); MERGE1(w, w0 + 3);
#undef MERGE1
                o4[i4] = ov;
            }
        }
    }
}

extern "C" void kernel_launch(void* const* d_in, const int* in_sizes, int n_in,
                              void* d_out, int out_size)
{
    const float* a          = (const float*)d_in[0];
    const float* b          = (const float*)d_in[1];
    const float* layer_emb  = (const float*)d_in[2];
    const float* in_proj_w  = (const float*)d_in[3];
    const float* in_proj_b  = (const float*)d_in[4];
    const float* ln1_g      = (const float*)d_in[5];
    const float* ln1_b      = (const float*)d_in[6];
    const float* qkv_w      = (const float*)d_in[7];
    const float* qkv_b      = (const float*)d_in[8];
    const float* out_w      = (const float*)d_in[9];
    const float* out_b      = (const float*)d_in[10];
    const float* ln2_g      = (const float*)d_in[11];
    const float* ln2_b      = (const float*)d_in[12];
    const float* ffn_w1     = (const float*)d_in[13];
    const float* ffn_b1     = (const float*)d_in[14];
    const float* ffn_w2     = (const float*)d_in[15];
    const float* ffn_b2     = (const float*)d_in[16];
    const float* gate_w     = (const float*)d_in[17];
    const float* gate_b     = (const float*)d_in[18];
    const float* row_w      = (const float*)d_in[19];
    const float* row_b      = (const float*)d_in[20];
    const float* col_w      = (const float*)d_in[21];
    const float* col_b      = (const float*)d_in[22];
    const float* drow_w     = (const float*)d_in[23];
    const float* drow_b     = (const float*)d_in[24];
    const float* dcol_w     = (const float*)d_in[25];
    const float* dcol_b     = (const float*)d_in[26];
    const float* dscale     = (const float*)d_in[27];
    float* out              = (float*)d_out;

    int dev = 0;
    cudaGetDevice(&dev);
    int nsm = 0;
    cudaDeviceGetAttribute(&nsm, cudaDevAttrMultiProcessorCount, dev);
    int occ = 0;
    cudaOccupancyMaxActiveBlocksPerMultiprocessor(&occ, fused_kernel, THREADS, 0);
    if (occ < 1) occ = 1;
    int grid = nsm * occ;
    if (grid > NP) grid = NP;

    fused_kernel<<<grid, THREADS>>>(
        a, b, layer_emb, in_proj_w, in_proj_b,
        ln1_g, ln1_b, qkv_w, qkv_b, out_w, out_b,
        ln2_g, ln2_b, ffn_w1, ffn_b1, ffn_w2, ffn_b2,
        gate_w, gate_b, row_w, row_b, col_w, col_b,
        drow_w, drow_b, dcol_w, dcol_b, dscale,
        out, grid);
}

// round 4
// speedup vs baseline: 2.7407x; 2.7377x over previous
#include <cuda_runtime.h>
#include <math.h>

#define NB   64
#define NHP  64
#define NH_  64
#define NW_  64
#define ND   32
#define NDFF 64
#define PIX  (NH_*NW_)
#define NP   (NB*NHP)

// scratch: feat [B, HP, D]
__device__ float g_feat[NP * ND];

// ---------------------------------------------------------------------------
// Kernel 1: per-(b,hp) stats over 4096 elements + in_proj -> g_feat
// ---------------------------------------------------------------------------
__global__ __launch_bounds__(256) void stats_kernel(
    const float* __restrict__ a, const float* __restrict__ b,
    const float* __restrict__ layer_emb,
    const float* __restrict__ in_proj_w,   // [D,12]
    const float* __restrict__ in_proj_b)   // [D]
{
    const int p   = blockIdx.x;
    const int tid = threadIdx.x;
    const float4* a4 = (const float4*)(a + (size_t)p * PIX);
    const float4* b4 = (const float4*)(b + (size_t)p * PIX);

    float4 av0 = __ldg(&a4[tid]),       av1 = __ldg(&a4[tid + 256]);
    float4 av2 = __ldg(&a4[tid + 512]), av3 = __ldg(&a4[tid + 768]);
    float4 bv0 = __ldg(&b4[tid]),       bv1 = __ldg(&b4[tid + 256]);
    float4 bv2 = __ldg(&b4[tid + 512]), bv3 = __ldg(&b4[tid + 768]);

    float sa = 0.f, sa2 = 0.f, sb = 0.f, sb2 = 0.f, dt = 0.f;
    float mna =  3.4e38f, mxa = -3.4e38f;
    float mnb =  3.4e38f, mxb = -3.4e38f;
#define ACC(u, v)                                                   \
    { float _u = (u), _v = (v);                                      \
      sa += _u; sa2 += _u * _u; sb += _v; sb2 += _v * _v;            \
      dt += _u * _v;                                                 \
      mna = fminf(mna, _u); mxa = fmaxf(mxa, _u);                    \
      mnb = fminf(mnb, _v); mxb = fmaxf(mxb, _v); }
    ACC(av0.x, bv0.x); ACC(av0.y, bv0.y); ACC(av0.z, bv0.z); ACC(av0.w, bv0.w);
    ACC(av1.x, bv1.x); ACC(av1.y, bv1.y); ACC(av1.z, bv1.z); ACC(av1.w, bv1.w);
    ACC(av2.x, bv2.x); ACC(av2.y, bv2.y); ACC(av2.z, bv2.z); ACC(av2.w, bv2.w);
    ACC(av3.x, bv3.x); ACC(av3.y, bv3.y); ACC(av3.z, bv3.z); ACC(av3.w, bv3.w);
#undef ACC

#pragma unroll
    for (int o = 16; o; o >>= 1) {
        sa  += __shfl_down_sync(0xffffffffu, sa,  o);
        sa2 += __shfl_down_sync(0xffffffffu, sa2, o);
        sb  += __shfl_down_sync(0xffffffffu, sb,  o);
        sb2 += __shfl_down_sync(0xffffffffu, sb2, o);
        dt  += __shfl_down_sync(0xffffffffu, dt,  o);
        mna = fminf(mna, __shfl_down_sync(0xffffffffu, mna, o));
        mxa = fmaxf(mxa, __shfl_down_sync(0xffffffffu, mxa, o));
        mnb = fminf(mnb, __shfl_down_sync(0xffffffffu, mnb, o));
        mxb = fmaxf(mxb, __shfl_down_sync(0xffffffffu, mxb, o));
    }

    __shared__ float red[8][9];
    __shared__ float stats[12];
    const int w = tid >> 5, l = tid & 31;
    if (l == 0) {
        red[w][0] = sa;  red[w][1] = sa2; red[w][2] = sb;  red[w][3] = sb2;
        red[w][4] = dt;  red[w][5] = mna; red[w][6] = mxa; red[w][7] = mnb;
        red[w][8] = mxb;
    }
    __syncthreads();

    if (tid == 0) {
        float SA = red[0][0], SA2 = red[0][1], SB = red[0][2], SB2 = red[0][3];
        float DT = red[0][4], MNA = red[0][5], MXA = red[0][6];
        float MNB = red[0][7], MXB = red[0][8];
#pragma unroll
        for (int i = 1; i < 8; i++) {
            SA += red[i][0]; SA2 += red[i][1]; SB += red[i][2]; SB2 += red[i][3];
            DT += red[i][4];
            MNA = fminf(MNA, red[i][5]); MXA = fmaxf(MXA, red[i][6]);
            MNB = fminf(MNB, red[i][7]); MXB = fmaxf(MXB, red[i][8]);
        }
        const float n = (float)PIX;
        const float invn = 1.f / n, invn1 = 1.f / (n - 1.f);
        float mean_a = SA * invn;
        float std_a  = sqrtf(fmaxf((SA2 - SA * SA * invn) * invn1, 0.f));
        float mean_b = SB * invn;
        float std_b  = sqrtf(fmaxf((SB2 - SB * SB * invn) * invn1, 0.f));
        float na = sqrtf(SA2), nb = sqrtf(SB2);
        float cosv = DT / (fmaxf(na, 1e-8f) * fmaxf(nb, 1e-8f));
        float SD  = SA - SB;
        float SD2 = SA2 + SB2 - 2.f * DT;
        float mean_d = SD * invn;
        float std_d  = sqrtf(fmaxf((SD2 - SD * SD * invn) * invn1, 0.f));
        float norm_d = sqrtf(fmaxf(SD2, 0.f));
        stats[0] = mean_a; stats[1] = std_a; stats[2] = MNA;  stats[3] = MXA;
        stats[4] = mean_b; stats[5] = std_b; stats[6] = MNB;  stats[7] = MXB;
        stats[8] = mean_d; stats[9] = std_d; stats[10] = norm_d; stats[11] = cosv;
    }
    __syncthreads();

    if (tid < ND) {
        float s = __ldg(&in_proj_b[tid]) + __ldg(&layer_emb[tid]);
#pragma unroll
        for (int j = 0; j < 12; j++)
            s += stats[j] * __ldg(&in_proj_w[tid * 12 + j]);
        g_feat[(size_t)p * ND + tid] = s;
    }
}

// ---------------------------------------------------------------------------
// Kernel 2: per-batch tiny transformer; weights transposed in smem (padded)
// ---------------------------------------------------------------------------
// dynamic smem layout (floats):
#define XF_SFEAT 0                       // [64][32]  2048
#define XF_SX    (XF_SFEAT + 2048)       // [64][32]  2048
#define XF_SQKV  (XF_SX + 2048)          // [64][96]  6144
#define XF_WQ    (XF_SQKV + 6144)        // [32][97]  3104
#define XF_WO    (XF_WQ + 3104)          // [32][33]  1056
#define XF_W1    (XF_WO + 1056)          // [32][65]  2080
#define XF_W2    (XF_W1 + 2080)          // [64][33]  2112
#define XF_TOTAL (XF_W2 + 2112)          // 18592 floats = 74368 B

__global__ __launch_bounds__(256) void xform_kernel(
    const float* __restrict__ ln1_g, const float* __restrict__ ln1_b,
    const float* __restrict__ qkv_w, const float* __restrict__ qkv_b,
    const float* __restrict__ out_w, const float* __restrict__ out_b,
    const float* __restrict__ ln2_g, const float* __restrict__ ln2_b,
    const float* __restrict__ w1,    const float* __restrict__ b1,
    const float* __restrict__ w2,    const float* __restrict__ b2)
{
    extern __shared__ float sm[];
    float* sfeat = sm + XF_SFEAT;   // [t][d] stride 32
    float* sx    = sm + XF_SX;
    float* sqkv  = sm + XF_SQKV;    // [t][j] stride 96
    float* wq    = sm + XF_WQ;      // [k][j] stride 97
    float* wo    = sm + XF_WO;      // [k][d] stride 33
    float* w1t   = sm + XF_W1;      // [k][j] stride 65
    float* w2t   = sm + XF_W2;      // [k][d] stride 33

    const int bb  = blockIdx.x;
    const int tid = threadIdx.x;
    float* gf = g_feat + (size_t)bb * NHP * ND;

    // stage transposed weights (coalesced gmem reads, conflict-free smem writes)
    for (int i = tid; i < 96 * 32; i += 256) {
        int j = i >> 5, k = i & 31;
        wq[k * 97 + j] = __ldg(&qkv_w[i]);
    }
    for (int i = tid; i < 32 * 32; i += 256) {
        int j = i >> 5, k = i & 31;
        wo[k * 33 + j] = __ldg(&out_w[i]);
    }
    for (int i = tid; i < 64 * 32; i += 256) {
        int j = i >> 5, k = i & 31;
        w1t[k * 65 + j] = __ldg(&w1[i]);
    }
    for (int i = tid; i < 32 * 64; i += 256) {
        int d = i >> 6, k = i & 63;
        w2t[k * 33 + d] = __ldg(&w2[i]);
    }
    for (int i = tid; i < NHP * ND; i += 256) sfeat[i] = gf[i];
    __syncthreads();

    // LN1
    if (tid < NHP) {
        float m = 0.f;
#pragma unroll
        for (int d = 0; d < ND; d++) m += sfeat[tid * ND + d];
        m *= (1.f / ND);
        float v = 0.f;
#pragma unroll
        for (int d = 0; d < ND; d++) { float t = sfeat[tid * ND + d] - m; v += t * t; }
        float r = rsqrtf(v * (1.f / ND) + 1e-5f);
#pragma unroll
        for (int d = 0; d < ND; d++)
            sx[tid * ND + d] = (sfeat[tid * ND + d] - m) * r * __ldg(&ln1_g[d]) + __ldg(&ln1_b[d]);
    }
    __syncthreads();

    // QKV
    for (int i = tid; i < NHP * 96; i += 256) {
        int t = i / 96, j = i - t * 96;
        float s = __ldg(&qkv_b[j]);
#pragma unroll
        for (int k = 0; k < ND; k++) s += sx[t * ND + k] * wq[k * 97 + j];
        sqkv[i] = s;
    }
    __syncthreads();

    // attention (thread = query token x head)
    if (tid < 128) {
        int qt = tid >> 1, h = tid & 1;
        float qv[16];
#pragma unroll
        for (int d = 0; d < 16; d++) qv[d] = sqkv[qt * 96 + h * 16 + d];
        float mx = -3.4e38f;
        for (int kk = 0; kk < NHP; kk++) {
            float s = 0.f;
#pragma unroll
            for (int d = 0; d < 16; d++) s += qv[d] * sqkv[kk * 96 + 32 + h * 16 + d];
            mx = fmaxf(mx, s * 0.25f);
        }
        float den = 0.f;
        float acc[16];
#pragma unroll
        for (int d = 0; d < 16; d++) acc[d] = 0.f;
        for (int kk = 0; kk < NHP; kk++) {
            float s = 0.f;
#pragma unroll
            for (int d = 0; d < 16; d++) s += qv[d] * sqkv[kk * 96 + 32 + h * 16 + d];
            float e = __expf(s * 0.25f - mx);
            den += e;
#pragma unroll
            for (int d = 0; d < 16; d++) acc[d] += e * sqkv[kk * 96 + 64 + h * 16 + d];
        }
        float inv = __fdividef(1.f, den);
#pragma unroll
        for (int d = 0; d < 16; d++) sx[qt * ND + h * 16 + d] = acc[d] * inv;
    }
    __syncthreads();

    // out proj + residual
    for (int i = tid; i < NHP * ND; i += 256) {
        int t = i >> 5, d = i & 31;
        float s = __ldg(&out_b[d]);
#pragma unroll
        for (int k = 0; k < ND; k++) s += sx[t * ND + k] * wo[k * 33 + d];
        sfeat[i] += s;
    }
    __syncthreads();

    // LN2
    if (tid < NHP) {
        float m = 0.f;
#pragma unroll
        for (int d = 0; d < ND; d++) m += sfeat[tid * ND + d];
        m *= (1.f / ND);
        float v = 0.f;
#pragma unroll
        for (int d = 0; d < ND; d++) { float t = sfeat[tid * ND + d] - m; v += t * t; }
        float r = rsqrtf(v * (1.f / ND) + 1e-5f);
#pragma unroll
        for (int d = 0; d < ND; d++)
            sx[tid * ND + d] = (sfeat[tid * ND + d] - m) * r * __ldg(&ln2_g[d]) + __ldg(&ln2_b[d]);
    }
    __syncthreads();

    // FFN1 + exact GELU (into sqkv, stride 64 now)
    for (int i = tid; i < NHP * NDFF; i += 256) {
        int t = i >> 6, j = i & 63;
        float s = __ldg(&b1[j]);
#pragma unroll
        for (int k = 0; k < ND; k++) s += sx[t * ND + k] * w1t[k * 65 + j];
        sqkv[t * NDFF + j] = 0.5f * s * (1.f + erff(s * 0.70710678118654752f));
    }
    __syncthreads();

    // FFN2 + residual
    for (int i = tid; i < NHP * ND; i += 256) {
        int t = i >> 5, d = i & 31;
        float s = __ldg(&b2[d]);
#pragma unroll
        for (int k = 0; k < NDFF; k++) s += sqkv[t * NDFF + k] * w2t[k * 33 + d];
        sfeat[i] += s;
    }
    __syncthreads();

    for (int i = tid; i < NHP * ND; i += 256) gf[i] = sfeat[i];
}

// ---------------------------------------------------------------------------
// Kernel 3: persistent heads + merge; transposed head weights in smem
// ---------------------------------------------------------------------------
__global__ __launch_bounds__(256) void merge_kernel(
    const float* __restrict__ a, const float* __restrict__ b,
    const float* __restrict__ gate_w, const float* __restrict__ gate_b,
    const float* __restrict__ row_w,  const float* __restrict__ row_b,
    const float* __restrict__ col_w,  const float* __restrict__ col_b,
    const float* __restrict__ drow_w, const float* __restrict__ drow_b,
    const float* __restrict__ dcol_w, const float* __restrict__ dcol_b,
    const float* __restrict__ delta_scale,
    float* __restrict__ out)
{
    __shared__ float srow[32 * 65];   // [k][j]
    __shared__ float scol[32 * 65];
    __shared__ float sdr [32 * 65];
    __shared__ float sdc [32 * 65];
    __shared__ float sbias[4 * 64];   // row_b, col_b, drow_b, dcol_b
    __shared__ float sgw[32];
    __shared__ float f[32];
    __shared__ float rowg[64], colv[64], drv[64], dcv[64];

    const int tid = threadIdx.x;

    // stage weights once per block
    for (int i = tid; i < 64 * 32; i += 256) {
        int j = i >> 5, k = i & 31;
        srow[k * 65 + j] = __ldg(&row_w[i]);
        scol[k * 65 + j] = __ldg(&col_w[i]);
        sdr [k * 65 + j] = __ldg(&drow_w[i]);
        sdc [k * 65 + j] = __ldg(&dcol_w[i]);
    }
    if (tid < 64) {
        sbias[tid]       = __ldg(&row_b[tid]);
        sbias[64 + tid]  = __ldg(&col_b[tid]);
        sbias[128 + tid] = __ldg(&drow_b[tid]);
        sbias[192 + tid] = __ldg(&dcol_b[tid]);
    }
    if (tid < 32) sgw[tid] = __ldg(&gate_w[tid]);
    const float gb = __ldg(&gate_b[0]);
    const float ds = __ldg(&delta_scale[0]);
    __syncthreads();

    for (int p = blockIdx.x; p < NP; p += gridDim.x) {
        __syncthreads();   // protect reuse of f/rowg/... across iterations
        if (tid < ND) f[tid] = g_feat[(size_t)p * ND + tid];
        __syncthreads();

        {
            float gate = gb;
#pragma unroll
            for (int k = 0; k < ND; k++) gate += f[k] * sgw[k];

            const int j   = tid & 63;
            const int grp = tid >> 6;
            const float* wt = (grp == 0) ? srow : (grp == 1) ? scol
                            : (grp == 2) ? sdr  : sdc;
            float s = sbias[grp * 64 + j];
#pragma unroll
            for (int k = 0; k < ND; k++) s += f[k] * wt[k * 65 + j];
            if (grp == 0)      rowg[j] = gate + s;
            else if (grp == 1) colv[j] = s;
            else if (grp == 2) drv[j]  = s * ds;
            else               dcv[j]  = s;
        }
        __syncthreads();

        const float4* a4 = (const float4*)(a + (size_t)p * PIX);
        const float4* b4 = (const float4*)(b + (size_t)p * PIX);
        float4*       o4 = (float4*)out + (size_t)p * (PIX / 4);

#pragma unroll
        for (int it = 0; it < 4; it++) {
            int i4 = tid + it * 256;
            int h  = i4 >> 4;
            int w0 = (i4 & 15) << 2;
            float4 av = __ldg(&a4[i4]);
            float4 bv = __ldg(&b4[i4]);
            float rg = rowg[h];
            float dr = drv[h];
            float4 ov;
#define MERGE1(comp, wi)                                                   \
            { float lgt = rg + colv[wi];                                    \
              float m = __fdividef(1.f, 1.f + __expf(-lgt));                \
              ov.comp = bv.comp + m * (av.comp - bv.comp) + dr * dcv[wi]; }
            MERGE1(x, w0 + 0); MERGE1(y, w0 + 1);
            MERGE1(z, w0 + 2); MERGE1(w, w0 + 3);
#undef MERGE1
            o4[i4] = ov;
        }
    }
}

// ---------------------------------------------------------------------------
extern "C" void kernel_launch(void* const* d_in, const int* in_sizes, int n_in,
                              void* d_out, int out_size)
{
    const float* a          = (const float*)d_in[0];
    const float* b          = (const float*)d_in[1];
    const float* layer_emb  = (const float*)d_in[2];
    const float* in_proj_w  = (const float*)d_in[3];
    const float* in_proj_b  = (const float*)d_in[4];
    const float* ln1_g      = (const float*)d_in[5];
    const float* ln1_b      = (const float*)d_in[6];
    const float* qkv_w      = (const float*)d_in[7];
    const float* qkv_b      = (const float*)d_in[8];
    const float* out_w      = (const float*)d_in[9];
    const float* out_b      = (const float*)d_in[10];
    const float* ln2_g      = (const float*)d_in[11];
    const float* ln2_b      = (const float*)d_in[12];
    const float* ffn_w1     = (const float*)d_in[13];
    const float* ffn_b1     = (const float*)d_in[14];
    const float* ffn_w2     = (const float*)d_in[15];
    const float* ffn_b2     = (const float*)d_in[16];
    const float* gate_w     = (const float*)d_in[17];
    const float* gate_b     = (const float*)d_in[18];
    const float* row_w      = (const float*)d_in[19];
    const float* row_b      = (const float*)d_in[20];
    const float* col_w      = (const float*)d_in[21];
    const float* col_b      = (const float*)d_in[22];
    const float* drow_w     = (const float*)d_in[23];
    const float* drow_b     = (const float*)d_in[24];
    const float* dcol_w     = (const float*)d_in[25];
    const float* dcol_b     = (const float*)d_in[26];
    const float* dscale     = (const float*)d_in[27];
    float* out              = (float*)d_out;

    int xf_smem = XF_TOTAL * (int)sizeof(float);
    cudaFuncSetAttribute(xform_kernel,
                         cudaFuncAttributeMaxDynamicSharedMemorySize, xf_smem);

    int dev = 0;
    cudaGetDevice(&dev);
    int nsm = 0;
    cudaDeviceGetAttribute(&nsm, cudaDevAttrMultiProcessorCount, dev);
    int mgrid = nsm * 6;
    if (mgrid > NP) mgrid = NP;

    stats_kernel<<<NP, 256>>>(a, b, layer_emb, in_proj_w, in_proj_b);
    xform_kernel<<<NB, 256, xf_smem>>>(ln1_g, ln1_b, qkv_w, qkv_b, out_w, out_b,
                                       ln2_g, ln2_b, ffn_w1, ffn_b1, ffn_w2, ffn_b2);
    merge_kernel<<<mgrid, 256>>>(a, b, gate_w, gate_b, row_w, row_b,
                                 col_w, col_b, drow_w, drow_b, dcol_w, dcol_b,
                                 dscale, out);
}

// round 5
// speedup vs baseline: 3.0346x; 1.1072x over previous
#include <cuda_runtime.h>
#include <math.h>

#define NB   64
#define NHP  64
#define NH_  64
#define NW_  64
#define ND   32
#define NDFF 64
#define PIX  (NH_*NW_)
#define NP   (NB*NHP)

// scratch
__device__ float g_feat[NP * ND];                        // [p][32]
__device__ __align__(16) float g_heads[NP * 256];        // [p]: [0,64)=rowg  [64,128)=drv  [128,192)=colv  [192,256)=dcv

// ---------------------------------------------------------------------------
// Kernel 1: per-(b,hp) stats over 4096 elements + in_proj -> g_feat
// ---------------------------------------------------------------------------
__global__ __launch_bounds__(256) void stats_kernel(
    const float* __restrict__ a, const float* __restrict__ b,
    const float* __restrict__ layer_emb,
    const float* __restrict__ in_proj_w,   // [D,12]
    const float* __restrict__ in_proj_b)   // [D]
{
    const int p   = blockIdx.x;
    const int tid = threadIdx.x;
    const float4* a4 = (const float4*)(a + (size_t)p * PIX);
    const float4* b4 = (const float4*)(b + (size_t)p * PIX);

    float4 av0 = __ldg(&a4[tid]),       av1 = __ldg(&a4[tid + 256]);
    float4 av2 = __ldg(&a4[tid + 512]), av3 = __ldg(&a4[tid + 768]);
    float4 bv0 = __ldg(&b4[tid]),       bv1 = __ldg(&b4[tid + 256]);
    float4 bv2 = __ldg(&b4[tid + 512]), bv3 = __ldg(&b4[tid + 768]);

    float sa = 0.f, sa2 = 0.f, sb = 0.f, sb2 = 0.f, dt = 0.f;
    float mna =  3.4e38f, mxa = -3.4e38f;
    float mnb =  3.4e38f, mxb = -3.4e38f;
#define ACC(u, v)                                                   \
    { float _u = (u), _v = (v);                                      \
      sa += _u; sa2 += _u * _u; sb += _v; sb2 += _v * _v;            \
      dt += _u * _v;                                                 \
      mna = fminf(mna, _u); mxa = fmaxf(mxa, _u);                    \
      mnb = fminf(mnb, _v); mxb = fmaxf(mxb, _v); }
    ACC(av0.x, bv0.x); ACC(av0.y, bv0.y); ACC(av0.z, bv0.z); ACC(av0.w, bv0.w);
    ACC(av1.x, bv1.x); ACC(av1.y, bv1.y); ACC(av1.z, bv1.z); ACC(av1.w, bv1.w);
    ACC(av2.x, bv2.x); ACC(av2.y, bv2.y); ACC(av2.z, bv2.z); ACC(av2.w, bv2.w);
    ACC(av3.x, bv3.x); ACC(av3.y, bv3.y); ACC(av3.z, bv3.z); ACC(av3.w, bv3.w);
#undef ACC

#pragma unroll
    for (int o = 16; o; o >>= 1) {
        sa  += __shfl_down_sync(0xffffffffu, sa,  o);
        sa2 += __shfl_down_sync(0xffffffffu, sa2, o);
        sb  += __shfl_down_sync(0xffffffffu, sb,  o);
        sb2 += __shfl_down_sync(0xffffffffu, sb2, o);
        dt  += __shfl_down_sync(0xffffffffu, dt,  o);
        mna = fminf(mna, __shfl_down_sync(0xffffffffu, mna, o));
        mxa = fmaxf(mxa, __shfl_down_sync(0xffffffffu, mxa, o));
        mnb = fminf(mnb, __shfl_down_sync(0xffffffffu, mnb, o));
        mxb = fmaxf(mxb, __shfl_down_sync(0xffffffffu, mxb, o));
    }

    __shared__ float red[8][9];
    __shared__ float stats[12];
    const int w = tid >> 5, l = tid & 31;
    if (l == 0) {
        red[w][0] = sa;  red[w][1] = sa2; red[w][2] = sb;  red[w][3] = sb2;
        red[w][4] = dt;  red[w][5] = mna; red[w][6] = mxa; red[w][7] = mnb;
        red[w][8] = mxb;
    }
    __syncthreads();

    if (tid == 0) {
        float SA = red[0][0], SA2 = red[0][1], SB = red[0][2], SB2 = red[0][3];
        float DT = red[0][4], MNA = red[0][5], MXA = red[0][6];
        float MNB = red[0][7], MXB = red[0][8];
#pragma unroll
        for (int i = 1; i < 8; i++) {
            SA += red[i][0]; SA2 += red[i][1]; SB += red[i][2]; SB2 += red[i][3];
            DT += red[i][4];
            MNA = fminf(MNA, red[i][5]); MXA = fmaxf(MXA, red[i][6]);
            MNB = fminf(MNB, red[i][7]); MXB = fmaxf(MXB, red[i][8]);
        }
        const float n = (float)PIX;
        const float invn = 1.f / n, invn1 = 1.f / (n - 1.f);
        float mean_a = SA * invn;
        float std_a  = sqrtf(fmaxf((SA2 - SA * SA * invn) * invn1, 0.f));
        float mean_b = SB * invn;
        float std_b  = sqrtf(fmaxf((SB2 - SB * SB * invn) * invn1, 0.f));
        float na = sqrtf(SA2), nb = sqrtf(SB2);
        float cosv = DT / (fmaxf(na, 1e-8f) * fmaxf(nb, 1e-8f));
        float SD  = SA - SB;
        float SD2 = SA2 + SB2 - 2.f * DT;
        float mean_d = SD * invn;
        float std_d  = sqrtf(fmaxf((SD2 - SD * SD * invn) * invn1, 0.f));
        float norm_d = sqrtf(fmaxf(SD2, 0.f));
        stats[0] = mean_a; stats[1] = std_a; stats[2] = MNA;  stats[3] = MXA;
        stats[4] = mean_b; stats[5] = std_b; stats[6] = MNB;  stats[7] = MXB;
        stats[8] = mean_d; stats[9] = std_d; stats[10] = norm_d; stats[11] = cosv;
    }
    __syncthreads();

    if (tid < ND) {
        float s = __ldg(&in_proj_b[tid]) + __ldg(&layer_emb[tid]);
#pragma unroll
        for (int j = 0; j < 12; j++)
            s += stats[j] * __ldg(&in_proj_w[tid * 12 + j]);
        g_feat[(size_t)p * ND + tid] = s;
    }
}

// ---------------------------------------------------------------------------
// Kernel 2: per-batch tiny transformer; smem weights + float4 activation reads
// ---------------------------------------------------------------------------
#define XF_SFEAT 0                       // [64][32]  2048
#define XF_SX    (XF_SFEAT + 2048)       // [64][32]  2048
#define XF_SQKV  (XF_SX + 2048)          // [64][96]  6144
#define XF_WQ    (XF_SQKV + 6144)        // [32][97]  3104
#define XF_WO    (XF_WQ + 3104)          // [32][33]  1056
#define XF_W1    (XF_WO + 1056)          // [32][65]  2080
#define XF_W2    (XF_W1 + 2080)          // [64][33]  2112
#define XF_TOTAL (XF_W2 + 2112)          // 18592 floats = 74368 B

__device__ __forceinline__ float dot4(float4 a, float4 b) {
    return fmaf(a.x, b.x, fmaf(a.y, b.y, fmaf(a.z, b.z, a.w * b.w)));
}

__global__ __launch_bounds__(256) void xform_kernel(
    const float* __restrict__ ln1_g, const float* __restrict__ ln1_b,
    const float* __restrict__ qkv_w, const float* __restrict__ qkv_b,
    const float* __restrict__ out_w, const float* __restrict__ out_b,
    const float* __restrict__ ln2_g, const float* __restrict__ ln2_b,
    const float* __restrict__ w1,    const float* __restrict__ b1,
    const float* __restrict__ w2,    const float* __restrict__ b2)
{
    extern __shared__ float sm[];
    float* sfeat = sm + XF_SFEAT;   // [t][d] stride 32
    float* sx    = sm + XF_SX;
    float* sqkv  = sm + XF_SQKV;    // [t][j] stride 96
    float* wq    = sm + XF_WQ;      // [k][j] stride 97
    float* wo    = sm + XF_WO;      // [k][d] stride 33
    float* w1t   = sm + XF_W1;      // [k][j] stride 65
    float* w2t   = sm + XF_W2;      // [k][d] stride 33

    const int bb  = blockIdx.x;
    const int tid = threadIdx.x;
    float* gf = g_feat + (size_t)bb * NHP * ND;

    for (int i = tid; i < 96 * 32; i += 256) {
        int j = i >> 5, k = i & 31;
        wq[k * 97 + j] = __ldg(&qkv_w[i]);
    }
    for (int i = tid; i < 32 * 32; i += 256) {
        int j = i >> 5, k = i & 31;
        wo[k * 33 + j] = __ldg(&out_w[i]);
    }
    for (int i = tid; i < 64 * 32; i += 256) {
        int j = i >> 5, k = i & 31;
        w1t[k * 65 + j] = __ldg(&w1[i]);
    }
    for (int i = tid; i < 32 * 64; i += 256) {
        int d = i >> 6, k = i & 63;
        w2t[k * 33 + d] = __ldg(&w2[i]);
    }
    for (int i = tid; i < NHP * ND; i += 256) sfeat[i] = gf[i];
    __syncthreads();

    // LN1
    if (tid < NHP) {
        float m = 0.f;
#pragma unroll
        for (int d = 0; d < ND; d++) m += sfeat[tid * ND + d];
        m *= (1.f / ND);
        float v = 0.f;
#pragma unroll
        for (int d = 0; d < ND; d++) { float t = sfeat[tid * ND + d] - m; v += t * t; }
        float r = rsqrtf(v * (1.f / ND) + 1e-5f);
#pragma unroll
        for (int d = 0; d < ND; d++)
            sx[tid * ND + d] = (sfeat[tid * ND + d] - m) * r * __ldg(&ln1_g[d]) + __ldg(&ln1_b[d]);
    }
    __syncthreads();

    // QKV (float4 activation broadcast)
    for (int i = tid; i < NHP * 96; i += 256) {
        int t = i / 96, j = i - t * 96;
        const float4* xv = (const float4*)(sx + t * ND);
        float s = __ldg(&qkv_b[j]);
#pragma unroll
        for (int k4 = 0; k4 < 8; k4++) {
            float4 f = xv[k4];
            int k = k4 * 4;
            s = fmaf(f.x, wq[(k+0)*97+j], s);
            s = fmaf(f.y, wq[(k+1)*97+j], s);
            s = fmaf(f.z, wq[(k+2)*97+j], s);
            s = fmaf(f.w, wq[(k+3)*97+j], s);
        }
        sqkv[i] = s;
    }
    __syncthreads();

    // attention: thread = (query token, head); float4 K/V reads
    if (tid < 128) {
        int qt = tid >> 1, h = tid & 1;
        const float4* sq4 = (const float4*)sqkv;   // 24 float4 per token row
        const int qbase = qt * 24 + h * 4;
        float4 q0 = sq4[qbase], q1 = sq4[qbase+1], q2 = sq4[qbase+2], q3 = sq4[qbase+3];

        float mx = -3.4e38f;
        for (int kk = 0; kk < NHP; kk++) {
            const float4* kb = sq4 + kk * 24 + 8 + h * 4;
            float s = dot4(q0, kb[0]) + dot4(q1, kb[1]) + dot4(q2, kb[2]) + dot4(q3, kb[3]);
            mx = fmaxf(mx, s * 0.25f);
        }
        float den = 0.f;
        float4 ac0 = {0,0,0,0}, ac1 = {0,0,0,0}, ac2 = {0,0,0,0}, ac3 = {0,0,0,0};
        for (int kk = 0; kk < NHP; kk++) {
            const float4* kb = sq4 + kk * 24 + 8 + h * 4;
            float s = dot4(q0, kb[0]) + dot4(q1, kb[1]) + dot4(q2, kb[2]) + dot4(q3, kb[3]);
            float e = __expf(s * 0.25f - mx);
            den += e;
            const float4* vb = sq4 + kk * 24 + 16 + h * 4;
            float4 v0 = vb[0], v1 = vb[1], v2 = vb[2], v3 = vb[3];
            ac0.x = fmaf(e, v0.x, ac0.x); ac0.y = fmaf(e, v0.y, ac0.y);
            ac0.z = fmaf(e, v0.z, ac0.z); ac0.w = fmaf(e, v0.w, ac0.w);
            ac1.x = fmaf(e, v1.x, ac1.x); ac1.y = fmaf(e, v1.y, ac1.y);
            ac1.z = fmaf(e, v1.z, ac1.z); ac1.w = fmaf(e, v1.w, ac1.w);
            ac2.x = fmaf(e, v2.x, ac2.x); ac2.y = fmaf(e, v2.y, ac2.y);
            ac2.z = fmaf(e, v2.z, ac2.z); ac2.w = fmaf(e, v2.w, ac2.w);
            ac3.x = fmaf(e, v3.x, ac3.x); ac3.y = fmaf(e, v3.y, ac3.y);
            ac3.z = fmaf(e, v3.z, ac3.z); ac3.w = fmaf(e, v3.w, ac3.w);
        }
        float inv = __fdividef(1.f, den);
        float4* dst = (float4*)(sx + qt * ND + h * 16);
        float4 o0 = {ac0.x*inv, ac0.y*inv, ac0.z*inv, ac0.w*inv};
        float4 o1 = {ac1.x*inv, ac1.y*inv, ac1.z*inv, ac1.w*inv};
        float4 o2 = {ac2.x*inv, ac2.y*inv, ac2.z*inv, ac2.w*inv};
        float4 o3 = {ac3.x*inv, ac3.y*inv, ac3.z*inv, ac3.w*inv};
        dst[0] = o0; dst[1] = o1; dst[2] = o2; dst[3] = o3;
    }
    __syncthreads();

    // out proj + residual
    for (int i = tid; i < NHP * ND; i += 256) {
        int t = i >> 5, d = i & 31;
        const float4* xv = (const float4*)(sx + t * ND);
        float s = __ldg(&out_b[d]);
#pragma unroll
        for (int k4 = 0; k4 < 8; k4++) {
            float4 f = xv[k4];
            int k = k4 * 4;
            s = fmaf(f.x, wo[(k+0)*33+d], s);
            s = fmaf(f.y, wo[(k+1)*33+d], s);
            s = fmaf(f.z, wo[(k+2)*33+d], s);
            s = fmaf(f.w, wo[(k+3)*33+d], s);
        }
        sfeat[i] += s;
    }
    __syncthreads();

    // LN2
    if (tid < NHP) {
        float m = 0.f;
#pragma unroll
        for (int d = 0; d < ND; d++) m += sfeat[tid * ND + d];
        m *= (1.f / ND);
        float v = 0.f;
#pragma unroll
        for (int d = 0; d < ND; d++) { float t = sfeat[tid * ND + d] - m; v += t * t; }
        float r = rsqrtf(v * (1.f / ND) + 1e-5f);
#pragma unroll
        for (int d = 0; d < ND; d++)
            sx[tid * ND + d] = (sfeat[tid * ND + d] - m) * r * __ldg(&ln2_g[d]) + __ldg(&ln2_b[d]);
    }
    __syncthreads();

    // FFN1 + exact GELU
    for (int i = tid; i < NHP * NDFF; i += 256) {
        int t = i >> 6, j = i & 63;
        const float4* xv = (const float4*)(sx + t * ND);
        float s = __ldg(&b1[j]);
#pragma unroll
        for (int k4 = 0; k4 < 8; k4++) {
            float4 f = xv[k4];
            int k = k4 * 4;
            s = fmaf(f.x, w1t[(k+0)*65+j], s);
            s = fmaf(f.y, w1t[(k+1)*65+j], s);
            s = fmaf(f.z, w1t[(k+2)*65+j], s);
            s = fmaf(f.w, w1t[(k+3)*65+j], s);
        }
        sqkv[t * NDFF + j] = 0.5f * s * (1.f + erff(s * 0.70710678118654752f));
    }
    __syncthreads();

    // FFN2 + residual
    for (int i = tid; i < NHP * ND; i += 256) {
        int t = i >> 5, d = i & 31;
        const float4* hv = (const float4*)(sqkv + t * NDFF);
        float s = __ldg(&b2[d]);
#pragma unroll
        for (int k4 = 0; k4 < 16; k4++) {
            float4 f = hv[k4];
            int k = k4 * 4;
            s = fmaf(f.x, w2t[(k+0)*33+d], s);
            s = fmaf(f.y, w2t[(k+1)*33+d], s);
            s = fmaf(f.z, w2t[(k+2)*33+d], s);
            s = fmaf(f.w, w2t[(k+3)*33+d], s);
        }
        sfeat[i] += s;
    }
    __syncthreads();

    for (int i = tid; i < NHP * ND; i += 256) gf[i] = sfeat[i];
}

// ---------------------------------------------------------------------------
// Kernel 3: heads — register weights, float4 feat broadcast; 8 pairs/block
// ---------------------------------------------------------------------------
__global__ __launch_bounds__(256) void heads_kernel(
    const float* __restrict__ gate_w, const float* __restrict__ gate_b,
    const float* __restrict__ row_w,  const float* __restrict__ row_b,
    const float* __restrict__ col_w,  const float* __restrict__ col_b,
    const float* __restrict__ drow_w, const float* __restrict__ drow_b,
    const float* __restrict__ dcol_w, const float* __restrict__ dcol_b,
    const float* __restrict__ delta_scale)
{
    __shared__ float sfeat[8 * 32];
    const int tid = threadIdx.x;
    const int grp = tid >> 6, j = tid & 63;

    const float* W = (grp == 0) ? row_w : (grp == 1) ? col_w
                   : (grp == 2) ? drow_w : dcol_w;
    const float* Bv = (grp == 0) ? row_b : (grp == 1) ? col_b
                    : (grp == 2) ? drow_b : dcol_b;
    float4 wreg[8];
    const float4* wv = (const float4*)(W + j * 32);
#pragma unroll
    for (int i = 0; i < 8; i++) wreg[i] = __ldg(&wv[i]);
    const float bias = __ldg(&Bv[j]);

    float4 gw[8];
    if (grp == 0) {
        const float4* gv = (const float4*)gate_w;
#pragma unroll
        for (int i = 0; i < 8; i++) gw[i] = __ldg(&gv[i]);
    }
    const float gb = __ldg(&gate_b[0]);
    const float ds = __ldg(&delta_scale[0]);

    const int p0 = blockIdx.x * 8;
    sfeat[tid] = g_feat[p0 * ND + tid];    // 8 pairs x 32 feats, coalesced
    __syncthreads();

#pragma unroll
    for (int i = 0; i < 8; i++) {
        const float4* fv = (const float4*)(sfeat + i * 32);
        float s = bias, g = gb;
#pragma unroll
        for (int k4 = 0; k4 < 8; k4++) {
            float4 f = fv[k4];
            s = fmaf(f.x, wreg[k4].x, s);
            s = fmaf(f.y, wreg[k4].y, s);
            s = fmaf(f.z, wreg[k4].z, s);
            s = fmaf(f.w, wreg[k4].w, s);
            if (grp == 0) {
                g = fmaf(f.x, gw[k4].x, g);
                g = fmaf(f.y, gw[k4].y, g);
                g = fmaf(f.z, gw[k4].z, g);
                g = fmaf(f.w, gw[k4].w, g);
            }
        }
        int off; float val;
        if (grp == 0)      { off = j;        val = s + g;  }
        else if (grp == 1) { off = 128 + j;  val = s;      }
        else if (grp == 2) { off = 64 + j;   val = s * ds; }
        else               { off = 192 + j;  val = s;      }
        g_heads[(p0 + i) * 256 + off] = val;
    }
}

// ---------------------------------------------------------------------------
// Kernel 4: merge — pure stream, reversed order for L2 reuse
// ---------------------------------------------------------------------------
__global__ __launch_bounds__(256) void merge_kernel(
    const float* __restrict__ a, const float* __restrict__ b,
    float* __restrict__ out)
{
    const int chunk = gridDim.x - 1 - blockIdx.x;    // descending through memory
    const int gid = chunk * 256 + threadIdx.x;
    const int p  = gid >> 10;          // 1024 float4 per pair
    const int r  = gid & 1023;
    const int h  = r >> 4;
    const int w0 = r & 15;

    const float* hp = g_heads + p * 256;
    const float rg = __ldg(hp + h);
    const float dr = __ldg(hp + 64 + h);
    const float4 cv = __ldg((const float4*)(hp + 128) + w0);
    const float4 dc = __ldg((const float4*)(hp + 192) + w0);

    const float4 av = __ldcs((const float4*)a + gid);
    const float4 bv = __ldcs((const float4*)b + gid);

    float4 ov;
#define MERGE1(comp, cvc, dcc)                                          \
    { float lgt = rg + cvc;                                              \
      float m = __fdividef(1.f, 1.f + __expf(-lgt));                     \
      ov.comp = fmaf(m, av.comp - bv.comp, fmaf(dr, dcc, bv.comp)); }
    MERGE1(x, cv.x, dc.x); MERGE1(y, cv.y, dc.y);
    MERGE1(z, cv.z, dc.z); MERGE1(w, cv.w, dc.w);
#undef MERGE1
    __stcs((float4*)out + gid, ov);
}

// ---------------------------------------------------------------------------
extern "C" void kernel_launch(void* const* d_in, const int* in_sizes, int n_in,
                              void* d_out, int out_size)
{
    const float* a          = (const float*)d_in[0];
    const float* b          = (const float*)d_in[1];
    const float* layer_emb  = (const float*)d_in[2];
    const float* in_proj_w  = (const float*)d_in[3];
    const float* in_proj_b  = (const float*)d_in[4];
    const float* ln1_g      = (const float*)d_in[5];
    const float* ln1_b      = (const float*)d_in[6];
    const float* qkv_w      = (const float*)d_in[7];
    const float* qkv_b      = (const float*)d_in[8];
    const float* out_w      = (const float*)d_in[9];
    const float* out_b      = (const float*)d_in[10];
    const float* ln2_g      = (const float*)d_in[11];
    const float* ln2_b      = (const float*)d_in[12];
    const float* ffn_w1     = (const float*)d_in[13];
    const float* ffn_b1     = (const float*)d_in[14];
    const float* ffn_w2     = (const float*)d_in[15];
    const float* ffn_b2     = (const float*)d_in[16];
    const float* gate_w     = (const float*)d_in[17];
    const float* gate_b     = (const float*)d_in[18];
    const float* row_w      = (const float*)d_in[19];
    const float* row_b      = (const float*)d_in[20];
    const float* col_w      = (const float*)d_in[21];
    const float* col_b      = (const float*)d_in[22];
    const float* drow_w     = (const float*)d_in[23];
    const float* drow_b     = (const float*)d_in[24];
    const float* dcol_w     = (const float*)d_in[25];
    const float* dcol_b     = (const float*)d_in[26];
    const float* dscale     = (const float*)d_in[27];
    float* out              = (float*)d_out;

    int xf_smem = XF_TOTAL * (int)sizeof(float);
    cudaFuncSetAttribute(xform_kernel,
                         cudaFuncAttributeMaxDynamicSharedMemorySize, xf_smem);

    stats_kernel<<<NP, 256>>>(a, b, layer_emb, in_proj_w, in_proj_b);
    xform_kernel<<<NB, 256, xf_smem>>>(ln1_g, ln1_b, qkv_w, qkv_b, out_w, out_b,
                                       ln2_g, ln2_b, ffn_w1, ffn_b1, ffn_w2, ffn_b2);
    heads_kernel<<<NP / 8, 256>>>(gate_w, gate_b, row_w, row_b, col_w, col_b,
                                  drow_w, drow_b, dcol_w, dcol_b, dscale);
    merge_kernel<<<NP * PIX / 4 / 256, 256>>>(a, b, out);
}

// round 7
// speedup vs baseline: 3.4556x; 1.1387x over previous
#include <cuda_runtime.h>
#include <math.h>

#define NB   64
#define NHP  64
#define NH_  64
#define NW_  64
#define ND   32
#define NDFF 64
#define PIX  (NH_*NW_)
#define NP   (NB*NHP)
#define FULL 0xffffffffu

// scratch
__device__ float g_feat[NP * ND];                        // [token][32]
__device__ float g_qkv [NP * 96];                        // [token][96] q|k|v
__device__ float g_attn[NP * ND];                        // [token][32]
__device__ __align__(16) float g_heads[NP * 256];        // [p]: [0,64)=rowg [64,128)=drv [128,192)=colv [192,256)=dcv

// ---------------------------------------------------------------------------
// Kernel 1: per-(b,hp) stats over 4096 elements + in_proj -> g_feat
// ---------------------------------------------------------------------------
__global__ __launch_bounds__(256) void stats_kernel(
    const float* __restrict__ a, const float* __restrict__ b,
    const float* __restrict__ layer_emb,
    const float* __restrict__ in_proj_w,   // [D,12]
    const float* __restrict__ in_proj_b)   // [D]
{
    const int p   = blockIdx.x;
    const int tid = threadIdx.x;
    const float4* a4 = (const float4*)(a + (size_t)p * PIX);
    const float4* b4 = (const float4*)(b + (size_t)p * PIX);

    float4 av0 = __ldg(&a4[tid]),       av1 = __ldg(&a4[tid + 256]);
    float4 av2 = __ldg(&a4[tid + 512]), av3 = __ldg(&a4[tid + 768]);
    float4 bv0 = __ldg(&b4[tid]),       bv1 = __ldg(&b4[tid + 256]);
    float4 bv2 = __ldg(&b4[tid + 512]), bv3 = __ldg(&b4[tid + 768]);

    float sa = 0.f, sa2 = 0.f, sb = 0.f, sb2 = 0.f, dt = 0.f;
    float mna =  3.4e38f, mxa = -3.4e38f;
    float mnb =  3.4e38f, mxb = -3.4e38f;
#define ACC(u, v)                                                   \
    { float _u = (u), _v = (v);                                      \
      sa += _u; sa2 += _u * _u; sb += _v; sb2 += _v * _v;            \
      dt += _u * _v;                                                 \
      mna = fminf(mna, _u); mxa = fmaxf(mxa, _u);                    \
      mnb = fminf(mnb, _v); mxb = fmaxf(mxb, _v); }
    ACC(av0.x, bv0.x); ACC(av0.y, bv0.y); ACC(av0.z, bv0.z); ACC(av0.w, bv0.w);
    ACC(av1.x, bv1.x); ACC(av1.y, bv1.y); ACC(av1.z, bv1.z); ACC(av1.w, bv1.w);
    ACC(av2.x, bv2.x); ACC(av2.y, bv2.y); ACC(av2.z, bv2.z); ACC(av2.w, bv2.w);
    ACC(av3.x, bv3.x); ACC(av3.y, bv3.y); ACC(av3.z, bv3.z); ACC(av3.w, bv3.w);
#undef ACC

#pragma unroll
    for (int o = 16; o; o >>= 1) {
        sa  += __shfl_down_sync(FULL, sa,  o);
        sa2 += __shfl_down_sync(FULL, sa2, o);
        sb  += __shfl_down_sync(FULL, sb,  o);
        sb2 += __shfl_down_sync(FULL, sb2, o);
        dt  += __shfl_down_sync(FULL, dt,  o);
        mna = fminf(mna, __shfl_down_sync(FULL, mna, o));
        mxa = fmaxf(mxa, __shfl_down_sync(FULL, mxa, o));
        mnb = fminf(mnb, __shfl_down_sync(FULL, mnb, o));
        mxb = fmaxf(mxb, __shfl_down_sync(FULL, mxb, o));
    }

    __shared__ float red[8][9];
    __shared__ float stats[12];
    const int w = tid >> 5, l = tid & 31;
    if (l == 0) {
        red[w][0] = sa;  red[w][1] = sa2; red[w][2] = sb;  red[w][3] = sb2;
        red[w][4] = dt;  red[w][5] = mna; red[w][6] = mxa; red[w][7] = mnb;
        red[w][8] = mxb;
    }
    __syncthreads();

    if (tid == 0) {
        float SA = red[0][0], SA2 = red[0][1], SB = red[0][2], SB2 = red[0][3];
        float DT = red[0][4], MNA = red[0][5], MXA = red[0][6];
        float MNB = red[0][7], MXB = red[0][8];
#pragma unroll
        for (int i = 1; i < 8; i++) {
            SA += red[i][0]; SA2 += red[i][1]; SB += red[i][2]; SB2 += red[i][3];
            DT += red[i][4];
            MNA = fminf(MNA, red[i][5]); MXA = fmaxf(MXA, red[i][6]);
            MNB = fminf(MNB, red[i][7]); MXB = fmaxf(MXB, red[i][8]);
        }
        const float n = (float)PIX;
        const float invn = 1.f / n, invn1 = 1.f / (n - 1.f);
        float mean_a = SA * invn;
        float std_a  = sqrtf(fmaxf((SA2 - SA * SA * invn) * invn1, 0.f));
        float mean_b = SB * invn;
        float std_b  = sqrtf(fmaxf((SB2 - SB * SB * invn) * invn1, 0.f));
        float na = sqrtf(SA2), nb = sqrtf(SB2);
        float cosv = DT / (fmaxf(na, 1e-8f) * fmaxf(nb, 1e-8f));
        float SD  = SA - SB;
        float SD2 = SA2 + SB2 - 2.f * DT;
        float mean_d = SD * invn;
        float std_d  = sqrtf(fmaxf((SD2 - SD * SD * invn) * invn1, 0.f));
        float norm_d = sqrtf(fmaxf(SD2, 0.f));
        stats[0] = mean_a; stats[1] = std_a; stats[2] = MNA;  stats[3] = MXA;
        stats[4] = mean_b; stats[5] = std_b; stats[6] = MNB;  stats[7] = MXB;
        stats[8] = mean_d; stats[9] = std_d; stats[10] = norm_d; stats[11] = cosv;
    }
    __syncthreads();

    if (tid < ND) {
        float s = __ldg(&in_proj_b[tid]) + __ldg(&layer_emb[tid]);
#pragma unroll
        for (int j = 0; j < 12; j++)
            s += stats[j] * __ldg(&in_proj_w[tid * 12 + j]);
        g_feat[(size_t)p * ND + tid] = s;
    }
}

// ---------------------------------------------------------------------------
// X1: LN1 + QKV  — one warp per token, 8 tokens/block, 512 blocks
// ---------------------------------------------------------------------------
__global__ __launch_bounds__(256) void ln1_qkv_kernel(
    const float* __restrict__ ln1_g, const float* __restrict__ ln1_b,
    const float* __restrict__ qkv_w, const float* __restrict__ qkv_b)
{
    __shared__ float wq[32 * 97];   // transposed [k][j]
    __shared__ float sqb[96];
    const int tid = threadIdx.x;
    for (int i = tid; i < 96 * 32; i += 256) {
        int j = i >> 5, k = i & 31;
        wq[k * 97 + j] = __ldg(&qkv_w[i]);
    }
    if (tid < 96) sqb[tid] = __ldg(&qkv_b[tid]);
    __syncthreads();

    const int lane  = tid & 31;
    const int token = blockIdx.x * 8 + (tid >> 5);

    float f = g_feat[token * ND + lane];
    float m = f;
#pragma unroll
    for (int o = 16; o; o >>= 1) m += __shfl_xor_sync(FULL, m, o);
    m *= (1.f / ND);
    float d = f - m;
    float v = d * d;
#pragma unroll
    for (int o = 16; o; o >>= 1) v += __shfl_xor_sync(FULL, v, o);
    float r = rsqrtf(v * (1.f / ND) + 1e-5f);
    float x = d * r * __ldg(&ln1_g[lane]) + __ldg(&ln1_b[lane]);

    float s0 = sqb[lane], s1 = sqb[lane + 32], s2 = sqb[lane + 64];
#pragma unroll
    for (int k = 0; k < 32; k++) {
        float xk = __shfl_sync(FULL, x, k);
        s0 = fmaf(xk, wq[k * 97 + lane],      s0);
        s1 = fmaf(xk, wq[k * 97 + lane + 32], s1);
        s2 = fmaf(xk, wq[k * 97 + lane + 64], s2);
    }
    g_qkv[token * 96 + lane]      = s0;
    g_qkv[token * 96 + 32 + lane] = s1;
    g_qkv[token * 96 + 64 + lane] = s2;
}

// ---------------------------------------------------------------------------
// X2: attention — block per (batch, head), thread per query
// ---------------------------------------------------------------------------
__device__ __forceinline__ float dot4(float4 a, float4 b) {
    return fmaf(a.x, b.x, fmaf(a.y, b.y, fmaf(a.z, b.z, a.w * b.w)));
}

__global__ __launch_bounds__(64) void attn_kernel()
{
    __shared__ float4 sk[64 * 4];
    __shared__ float4 sv[64 * 4];
    const int bb = blockIdx.x >> 1;
    const int h  = blockIdx.x & 1;
    const int qt = threadIdx.x;          // 0..63

    // load K,V for this (batch, head): 64 tokens x 16 dims each
#pragma unroll
    for (int it = 0; it < 4; it++) {
        int idx = qt + it * 64;          // 256 float4 slots
        int tt = idx >> 2, quad = idx & 3;
        const float* base = g_qkv + (bb * 64 + tt) * 96 + h * 16 + quad * 4;
        sk[idx] = *(const float4*)(base + 32);
        sv[idx] = *(const float4*)(base + 64);
    }
    __syncthreads();

    const float* qb = g_qkv + (bb * 64 + qt) * 96 + h * 16;
    float4 q0 = *(const float4*)(qb),     q1 = *(const float4*)(qb + 4);
    float4 q2 = *(const float4*)(qb + 8), q3 = *(const float4*)(qb + 12);

    float mx = -3.4e38f;
    for (int kk = 0; kk < 64; kk++) {
        const float4* kb = sk + kk * 4;
        float s = dot4(q0, kb[0]) + dot4(q1, kb[1]) + dot4(q2, kb[2]) + dot4(q3, kb[3]);
        mx = fmaxf(mx, s * 0.25f);
    }
    float den = 0.f;
    float4 ac0 = {0,0,0,0}, ac1 = {0,0,0,0}, ac2 = {0,0,0,0}, ac3 = {0,0,0,0};
    for (int kk = 0; kk < 64; kk++) {
        const float4* kb = sk + kk * 4;
        float s = dot4(q0, kb[0]) + dot4(q1, kb[1]) + dot4(q2, kb[2]) + dot4(q3, kb[3]);
        float e = __expf(s * 0.25f - mx);
        den += e;
        const float4* vb = sv + kk * 4;
        float4 v0 = vb[0], v1 = vb[1], v2 = vb[2], v3 = vb[3];
        ac0.x = fmaf(e, v0.x, ac0.x); ac0.y = fmaf(e, v0.y, ac0.y);
        ac0.z = fmaf(e, v0.z, ac0.z); ac0.w = fmaf(e, v0.w, ac0.w);
        ac1.x = fmaf(e, v1.x, ac1.x); ac1.y = fmaf(e, v1.y, ac1.y);
        ac1.z = fmaf(e, v1.z, ac1.z); ac1.w = fmaf(e, v1.w, ac1.w);
        ac2.x = fmaf(e, v2.x, ac2.x); ac2.y = fmaf(e, v2.y, ac2.y);
        ac2.z = fmaf(e, v2.z, ac2.z); ac2.w = fmaf(e, v2.w, ac2.w);
        ac3.x = fmaf(e, v3.x, ac3.x); ac3.y = fmaf(e, v3.y, ac3.y);
        ac3.z = fmaf(e, v3.z, ac3.z); ac3.w = fmaf(e, v3.w, ac3.w);
    }
    float inv = __fdividef(1.f, den);
    float* dst = g_attn + (bb * 64 + qt) * ND + h * 16;
    float4 o0 = {ac0.x*inv, ac0.y*inv, ac0.z*inv, ac0.w*inv};
    float4 o1 = {ac1.x*inv, ac1.y*inv, ac1.z*inv, ac1.w*inv};
    float4 o2 = {ac2.x*inv, ac2.y*inv, ac2.z*inv, ac2.w*inv};
    float4 o3 = {ac3.x*inv, ac3.y*inv, ac3.z*inv, ac3.w*inv};
    *(float4*)(dst)      = o0;
    *(float4*)(dst + 4)  = o1;
    *(float4*)(dst + 8)  = o2;
    *(float4*)(dst + 12) = o3;
}

// ---------------------------------------------------------------------------
// X3: out proj + residual + LN2 + FFN + residual — warp per token
// ---------------------------------------------------------------------------
__global__ __launch_bounds__(256) void post_kernel(
    const float* __restrict__ out_w, const float* __restrict__ out_b,
    const float* __restrict__ ln2_g, const float* __restrict__ ln2_b,
    const float* __restrict__ w1,    const float* __restrict__ b1,
    const float* __restrict__ w2,    const float* __restrict__ b2)
{
    __shared__ float woT[32 * 33];
    __shared__ float w1T[32 * 65];
    __shared__ float w2T[64 * 33];
    __shared__ float sob[32], sb1[64], sb2[32];
    const int tid = threadIdx.x;

    for (int i = tid; i < 32 * 32; i += 256) {
        int j = i >> 5, k = i & 31;
        woT[k * 33 + j] = __ldg(&out_w[i]);
    }
    for (int i = tid; i < 64 * 32; i += 256) {
        int j = i >> 5, k = i & 31;
        w1T[k * 65 + j] = __ldg(&w1[i]);
    }
    for (int i = tid; i < 32 * 64; i += 256) {
        int d = i >> 6, k = i & 63;
        w2T[k * 33 + d] = __ldg(&w2[i]);
    }
    if (tid < 32) { sob[tid] = __ldg(&out_b[tid]); sb2[tid] = __ldg(&b2[tid]); }
    if (tid < 64) sb1[tid] = __ldg(&b1[tid]);
    __syncthreads();

    const int lane  = tid & 31;
    const int token = blockIdx.x * 8 + (tid >> 5);

    float ao = g_attn[token * ND + lane];
    float f  = g_feat[token * ND + lane];

    // out proj + residual
    float s = sob[lane];
#pragma unroll
    for (int k = 0; k < 32; k++) {
        float aok = __shfl_sync(FULL, ao, k);
        s = fmaf(aok, woT[k * 33 + lane], s);
    }
    f += s;

    // LN2
    float m = f;
#pragma unroll
    for (int o = 16; o; o >>= 1) m += __shfl_xor_sync(FULL, m, o);
    m *= (1.f / ND);
    float d = f - m;
    float v = d * d;
#pragma unroll
    for (int o = 16; o; o >>= 1) v += __shfl_xor_sync(FULL, v, o);
    float r = rsqrtf(v * (1.f / ND) + 1e-5f);
    float x = d * r * __ldg(&ln2_g[lane]) + __ldg(&ln2_b[lane]);

    // FFN1 + exact GELU
    float y0 = sb1[lane], y1 = sb1[lane + 32];
#pragma unroll
    for (int k = 0; k < 32; k++) {
        float xk = __shfl_sync(FULL, x, k);
        y0 = fmaf(xk, w1T[k * 65 + lane],      y0);
        y1 = fmaf(xk, w1T[k * 65 + lane + 32], y1);
    }
    y0 = 0.5f * y0 * (1.f + erff(y0 * 0.70710678118654752f));
    y1 = 0.5f * y1 * (1.f + erff(y1 * 0.70710678118654752f));

    // FFN2 + residual
    s = sb2[lane];
#pragma unroll
    for (int k = 0; k < 64; k++) {
        float yk = __shfl_sync(FULL, (k < 32) ? y0 : y1, k & 31);
        s = fmaf(yk, w2T[k * 33 + lane], s);
    }
    f += s;
    g_feat[token * ND + lane] = f;
}

// ---------------------------------------------------------------------------
// heads — register weights, float4 feat broadcast; 8 pairs/block
// ---------------------------------------------------------------------------
__global__ __launch_bounds__(256) void heads_kernel(
    const float* __restrict__ gate_w, const float* __restrict__ gate_b,
    const float* __restrict__ row_w,  const float* __restrict__ row_b,
    const float* __restrict__ col_w,  const float* __restrict__ col_b,
    const float* __restrict__ drow_w, const float* __restrict__ drow_b,
    const float* __restrict__ dcol_w, const float* __restrict__ dcol_b,
    const float* __restrict__ delta_scale)
{
    __shared__ float sfeat[8 * 32];
    const int tid = threadIdx.x;
    const int grp = tid >> 6, j = tid & 63;

    const float* W = (grp == 0) ? row_w : (grp == 1) ? col_w
                   : (grp == 2) ? drow_w : dcol_w;
    const float* Bv = (grp == 0) ? row_b : (grp == 1) ? col_b
                    : (grp == 2) ? drow_b : dcol_b;
    float4 wreg[8];
    const float4* wv = (const float4*)(W + j * 32);
#pragma unroll
    for (int i = 0; i < 8; i++) wreg[i] = __ldg(&wv[i]);
    const float bias = __ldg(&Bv[j]);

    float4 gw[8];
    if (grp == 0) {
        const float4* gv = (const float4*)gate_w;
#pragma unroll
        for (int i = 0; i < 8; i++) gw[i] = __ldg(&gv[i]);
    }
    const float gb = __ldg(&gate_b[0]);
    const float ds = __ldg(&delta_scale[0]);

    const int p0 = blockIdx.x * 8;
    sfeat[tid] = g_feat[p0 * ND + tid];
    __syncthreads();

#pragma unroll
    for (int i = 0; i < 8; i++) {
        const float4* fv = (const float4*)(sfeat + i * 32);
        float s = bias, g = gb;
#pragma unroll
        for (int k4 = 0; k4 < 8; k4++) {
            float4 f = fv[k4];
            s = fmaf(f.x, wreg[k4].x, s);
            s = fmaf(f.y, wreg[k4].y, s);
            s = fmaf(f.z, wreg[k4].z, s);
            s = fmaf(f.w, wreg[k4].w, s);
            if (grp == 0) {
                g = fmaf(f.x, gw[k4].x, g);
                g = fmaf(f.y, gw[k4].y, g);
                g = fmaf(f.z, gw[k4].z, g);
                g = fmaf(f.w, gw[k4].w, g);
            }
        }
        int off; float val;
        if (grp == 0)      { off = j;        val = s + g;  }
        else if (grp == 1) { off = 128 + j;  val = s;      }
        else if (grp == 2) { off = 64 + j;   val = s * ds; }
        else               { off = 192 + j;  val = s;      }
        g_heads[(p0 + i) * 256 + off] = val;
    }
}

// ---------------------------------------------------------------------------
// merge — pure stream, reversed order for L2 reuse
// ---------------------------------------------------------------------------
__global__ __launch_bounds__(256) void merge_kernel(
    const float* __restrict__ a, const float* __restrict__ b,
    float* __restrict__ out)
{
    const int chunk = gridDim.x - 1 - blockIdx.x;
    const int gid = chunk * 256 + threadIdx.x;
    const int p  = gid >> 10;
    const int r  = gid & 1023;
    const int h  = r >> 4;
    const int w0 = r & 15;

    const float* hp = g_heads + p * 256;
    const float rg = __ldg(hp + h);
    const float dr = __ldg(hp + 64 + h);
    const float4 cv = __ldg((const float4*)(hp + 128) + w0);
    const float4 dc = __ldg((const float4*)(hp + 192) + w0);

    const float4 av = __ldcs((const float4*)a + gid);
    const float4 bv = __ldcs((const float4*)b + gid);

    float4 ov;
#define MERGE1(comp, cvc, dcc)                                          \
    { float lgt = rg + cvc;                                              \
      float m = __fdividef(1.f, 1.f + __expf(-lgt));                     \
      ov.comp = fmaf(m, av.comp - bv.comp, fmaf(dr, dcc, bv.comp)); }
    MERGE1(x, cv.x, dc.x); MERGE1(y, cv.y, dc.y);
    MERGE1(z, cv.z, dc.z); MERGE1(w, cv.w, dc.w);
#undef MERGE1
    __stcs((float4*)out + gid, ov);
}

// ---------------------------------------------------------------------------
extern "C" void kernel_launch(void* const* d_in, const int* in_sizes, int n_in,
                              void* d_out, int out_size)
{
    const float* a          = (const float*)d_in[0];
    const float* b          = (const float*)d_in[1];
    const float* layer_emb  = (const float*)d_in[2];
    const float* in_proj_w  = (const float*)d_in[3];
    const float* in_proj_b  = (const float*)d_in[4];
    const float* ln1_g      = (const float*)d_in[5];
    const float* ln1_b      = (const float*)d_in[6];
    const float* qkv_w      = (const float*)d_in[7];
    const float* qkv_b      = (const float*)d_in[8];
    const float* out_w      = (const float*)d_in[9];
    const float* out_b      = (const float*)d_in[10];
    const float* ln2_g      = (const float*)d_in[11];
    const float* ln2_b      = (const float*)d_in[12];
    const float* ffn_w1     = (const float*)d_in[13];
    const float* ffn_b1     = (const float*)d_in[14];
    const float* ffn_w2     = (const float*)d_in[15];
    const float* ffn_b2     = (const float*)d_in[16];
    const float* gate_w     = (const float*)d_in[17];
    const float* gate_b     = (const float*)d_in[18];
    const float* row_w      = (const float*)d_in[19];
    const float* row_b      = (const float*)d_in[20];
    const float* col_w      = (const float*)d_in[21];
    const float* col_b      = (const float*)d_in[22];
    const float* drow_w     = (const float*)d_in[23];
    const float* drow_b     = (const float*)d_in[24];
    const float* dcol_w     = (const float*)d_in[25];
    const float* dcol_b     = (const float*)d_in[26];
    const float* dscale     = (const float*)d_in[27];
    float* out              = (float*)d_out;

    stats_kernel<<<NP, 256>>>(a, b, layer_emb, in_proj_w, in_proj_b);
    ln1_qkv_kernel<<<NP / 8, 256>>>(ln1_g, ln1_b, qkv_w, qkv_b);
    attn_kernel<<<NB * 2, 64>>>();
    post_kernel<<<NP / 8, 256>>>(out_w, out_b, ln2_g, ln2_b,
                                 ffn_w1, ffn_b1, ffn_w2, ffn_b2);
    heads_kernel<<<NP / 8, 256>>>(gate_w, gate_b, row_w, row_b, col_w, col_b,
                                  drow_w, drow_b, dcol_w, dcol_b, dscale);
    merge_kernel<<<NP * PIX / 4 / 256, 256>>>(a, b, out);
}

// round 8
// speedup vs baseline: 3.5372x; 1.0236x over previous
#include <cuda_runtime.h>
#include <math.h>

#define NB   64
#define NHP  64
#define NH_  64
#define NW_  64
#define ND   32
#define NDFF 64
#define PIX  (NH_*NW_)
#define NP   (NB*NHP)
#define FULL 0xffffffffu

// scratch
__device__ float g_feat[NP * ND];                        // [token][32]
__device__ float g_qkv [NP * 96];                        // [token][96] q|k|v
__device__ float g_attn[NP * ND];                        // [token][32]
__device__ __align__(16) float g_heads[NP * 256];        // [p]: [0,64)=rowg [64,128)=drv [128,192)=colv [192,256)=dcv

// ---------------------------------------------------------------------------
// Kernel 1: per-(b,hp) stats over 4096 elements + in_proj -> g_feat
// ---------------------------------------------------------------------------
__global__ __launch_bounds__(256) void stats_kernel(
    const float* __restrict__ a, const float* __restrict__ b,
    const float* __restrict__ layer_emb,
    const float* __restrict__ in_proj_w,   // [D,12]
    const float* __restrict__ in_proj_b)   // [D]
{
    const int p   = blockIdx.x;
    const int tid = threadIdx.x;
    const float4* a4 = (const float4*)(a + (size_t)p * PIX);
    const float4* b4 = (const float4*)(b + (size_t)p * PIX);

    float4 av0 = __ldg(&a4[tid]),       av1 = __ldg(&a4[tid + 256]);
    float4 av2 = __ldg(&a4[tid + 512]), av3 = __ldg(&a4[tid + 768]);
    float4 bv0 = __ldg(&b4[tid]),       bv1 = __ldg(&b4[tid + 256]);
    float4 bv2 = __ldg(&b4[tid + 512]), bv3 = __ldg(&b4[tid + 768]);

    float sa = 0.f, sa2 = 0.f, sb = 0.f, sb2 = 0.f, dt = 0.f;
    float mna =  3.4e38f, mxa = -3.4e38f;
    float mnb =  3.4e38f, mxb = -3.4e38f;
#define ACC(u, v)                                                   \
    { float _u = (u), _v = (v);                                      \
      sa += _u; sa2 += _u * _u; sb += _v; sb2 += _v * _v;            \
      dt += _u * _v;                                                 \
      mna = fminf(mna, _u); mxa = fmaxf(mxa, _u);                    \
      mnb = fminf(mnb, _v); mxb = fmaxf(mxb, _v); }
    ACC(av0.x, bv0.x); ACC(av0.y, bv0.y); ACC(av0.z, bv0.z); ACC(av0.w, bv0.w);
    ACC(av1.x, bv1.x); ACC(av1.y, bv1.y); ACC(av1.z, bv1.z); ACC(av1.w, bv1.w);
    ACC(av2.x, bv2.x); ACC(av2.y, bv2.y); ACC(av2.z, bv2.z); ACC(av2.w, bv2.w);
    ACC(av3.x, bv3.x); ACC(av3.y, bv3.y); ACC(av3.z, bv3.z); ACC(av3.w, bv3.w);
#undef ACC

#pragma unroll
    for (int o = 16; o; o >>= 1) {
        sa  += __shfl_down_sync(FULL, sa,  o);
        sa2 += __shfl_down_sync(FULL, sa2, o);
        sb  += __shfl_down_sync(FULL, sb,  o);
        sb2 += __shfl_down_sync(FULL, sb2, o);
        dt  += __shfl_down_sync(FULL, dt,  o);
        mna = fminf(mna, __shfl_down_sync(FULL, mna, o));
        mxa = fmaxf(mxa, __shfl_down_sync(FULL, mxa, o));
        mnb = fminf(mnb, __shfl_down_sync(FULL, mnb, o));
        mxb = fmaxf(mxb, __shfl_down_sync(FULL, mxb, o));
    }

    __shared__ float red[8][9];
    __shared__ float stats[12];
    const int w = tid >> 5, l = tid & 31;
    if (l == 0) {
        red[w][0] = sa;  red[w][1] = sa2; red[w][2] = sb;  red[w][3] = sb2;
        red[w][4] = dt;  red[w][5] = mna; red[w][6] = mxa; red[w][7] = mnb;
        red[w][8] = mxb;
    }
    __syncthreads();

    if (tid == 0) {
        float SA = red[0][0], SA2 = red[0][1], SB = red[0][2], SB2 = red[0][3];
        float DT = red[0][4], MNA = red[0][5], MXA = red[0][6];
        float MNB = red[0][7], MXB = red[0][8];
#pragma unroll
        for (int i = 1; i < 8; i++) {
            SA += red[i][0]; SA2 += red[i][1]; SB += red[i][2]; SB2 += red[i][3];
            DT += red[i][4];
            MNA = fminf(MNA, red[i][5]); MXA = fmaxf(MXA, red[i][6]);
            MNB = fminf(MNB, red[i][7]); MXB = fmaxf(MXB, red[i][8]);
        }
        const float n = (float)PIX;
        const float invn = 1.f / n, invn1 = 1.f / (n - 1.f);
        float mean_a = SA * invn;
        float std_a  = sqrtf(fmaxf((SA2 - SA * SA * invn) * invn1, 0.f));
        float mean_b = SB * invn;
        float std_b  = sqrtf(fmaxf((SB2 - SB * SB * invn) * invn1, 0.f));
        float na = sqrtf(SA2), nb = sqrtf(SB2);
        float cosv = DT / (fmaxf(na, 1e-8f) * fmaxf(nb, 1e-8f));
        float SD  = SA - SB;
        float SD2 = SA2 + SB2 - 2.f * DT;
        float mean_d = SD * invn;
        float std_d  = sqrtf(fmaxf((SD2 - SD * SD * invn) * invn1, 0.f));
        float norm_d = sqrtf(fmaxf(SD2, 0.f));
        stats[0] = mean_a; stats[1] = std_a; stats[2] = MNA;  stats[3] = MXA;
        stats[4] = mean_b; stats[5] = std_b; stats[6] = MNB;  stats[7] = MXB;
        stats[8] = mean_d; stats[9] = std_d; stats[10] = norm_d; stats[11] = cosv;
    }
    __syncthreads();

    if (tid < ND) {
        float s = __ldg(&in_proj_b[tid]) + __ldg(&layer_emb[tid]);
#pragma unroll
        for (int j = 0; j < 12; j++)
            s += stats[j] * __ldg(&in_proj_w[tid * 12 + j]);
        g_feat[(size_t)p * ND + tid] = s;
    }
}

// ---------------------------------------------------------------------------
// X1: LN1 + QKV — warp per token, smem activation broadcast (no shfl matvec)
// ---------------------------------------------------------------------------
__global__ __launch_bounds__(256) void ln1_qkv_kernel(
    const float* __restrict__ ln1_g, const float* __restrict__ ln1_b,
    const float* __restrict__ qkv_w, const float* __restrict__ qkv_b)
{
    __shared__ float wq[32 * 97];   // transposed [k][j]
    __shared__ float sqb[96];
    __shared__ __align__(16) float sx[8 * 32];

    const int tid  = threadIdx.x;
    const int lane = tid & 31;
    const int wtok = tid >> 5;
    const int token = blockIdx.x * 8 + wtok;

    for (int i = tid; i < 96 * 32; i += 256) {
        int j = i >> 5, k = i & 31;
        wq[k * 97 + j] = __ldg(&qkv_w[i]);
    }
    if (tid < 96) sqb[tid] = __ldg(&qkv_b[tid]);

    // LN1 (warp butterflies — cheap)
    float f = g_feat[token * ND + lane];
    float m = f;
#pragma unroll
    for (int o = 16; o; o >>= 1) m += __shfl_xor_sync(FULL, m, o);
    m *= (1.f / ND);
    float d = f - m;
    float v = d * d;
#pragma unroll
    for (int o = 16; o; o >>= 1) v += __shfl_xor_sync(FULL, v, o);
    float r = rsqrtf(v * (1.f / ND) + 1e-5f);
    sx[wtok * 32 + lane] = d * r * __ldg(&ln1_g[lane]) + __ldg(&ln1_b[lane]);
    __syncthreads();

    // QKV: 3 outputs per thread; activations via broadcast float4 LDS
    float s0 = sqb[lane], s1 = sqb[lane + 32], s2 = sqb[lane + 64];
    const float4* xv = (const float4*)(sx + wtok * 32);
#pragma unroll
    for (int k4 = 0; k4 < 8; k4++) {
        float4 xa = xv[k4];
        int k = k4 * 4;
        s0 = fmaf(xa.x, wq[(k+0)*97+lane],      s0);
        s0 = fmaf(xa.y, wq[(k+1)*97+lane],      s0);
        s0 = fmaf(xa.z, wq[(k+2)*97+lane],      s0);
        s0 = fmaf(xa.w, wq[(k+3)*97+lane],      s0);
        s1 = fmaf(xa.x, wq[(k+0)*97+lane+32],   s1);
        s1 = fmaf(xa.y, wq[(k+1)*97+lane+32],   s1);
        s1 = fmaf(xa.z, wq[(k+2)*97+lane+32],   s1);
        s1 = fmaf(xa.w, wq[(k+3)*97+lane+32],   s1);
        s2 = fmaf(xa.x, wq[(k+0)*97+lane+64],   s2);
        s2 = fmaf(xa.y, wq[(k+1)*97+lane+64],   s2);
        s2 = fmaf(xa.z, wq[(k+2)*97+lane+64],   s2);
        s2 = fmaf(xa.w, wq[(k+3)*97+lane+64],   s2);
    }
    g_qkv[token * 96 + lane]      = s0;
    g_qkv[token * 96 + 32 + lane] = s1;
    g_qkv[token * 96 + 64 + lane] = s2;
}

// ---------------------------------------------------------------------------
// X2: attention — block per (batch, head), thread per query
// ---------------------------------------------------------------------------
__device__ __forceinline__ float dot4(float4 a, float4 b) {
    return fmaf(a.x, b.x, fmaf(a.y, b.y, fmaf(a.z, b.z, a.w * b.w)));
}

__global__ __launch_bounds__(64) void attn_kernel()
{
    __shared__ float4 sk[64 * 4];
    __shared__ float4 sv[64 * 4];
    const int bb = blockIdx.x >> 1;
    const int h  = blockIdx.x & 1;
    const int qt = threadIdx.x;

#pragma unroll
    for (int it = 0; it < 4; it++) {
        int idx = qt + it * 64;
        int tt = idx >> 2, quad = idx & 3;
        const float* base = g_qkv + (bb * 64 + tt) * 96 + h * 16 + quad * 4;
        sk[idx] = *(const float4*)(base + 32);
        sv[idx] = *(const float4*)(base + 64);
    }
    __syncthreads();

    const float* qb = g_qkv + (bb * 64 + qt) * 96 + h * 16;
    float4 q0 = *(const float4*)(qb),     q1 = *(const float4*)(qb + 4);
    float4 q2 = *(const float4*)(qb + 8), q3 = *(const float4*)(qb + 12);

    float mx = -3.4e38f;
    for (int kk = 0; kk < 64; kk++) {
        const float4* kb = sk + kk * 4;
        float s = dot4(q0, kb[0]) + dot4(q1, kb[1]) + dot4(q2, kb[2]) + dot4(q3, kb[3]);
        mx = fmaxf(mx, s * 0.25f);
    }
    float den = 0.f;
    float4 ac0 = {0,0,0,0}, ac1 = {0,0,0,0}, ac2 = {0,0,0,0}, ac3 = {0,0,0,0};
    for (int kk = 0; kk < 64; kk++) {
        const float4* kb = sk + kk * 4;
        float s = dot4(q0, kb[0]) + dot4(q1, kb[1]) + dot4(q2, kb[2]) + dot4(q3, kb[3]);
        float e = __expf(s * 0.25f - mx);
        den += e;
        const float4* vb = sv + kk * 4;
        float4 v0 = vb[0], v1 = vb[1], v2 = vb[2], v3 = vb[3];
        ac0.x = fmaf(e, v0.x, ac0.x); ac0.y = fmaf(e, v0.y, ac0.y);
        ac0.z = fmaf(e, v0.z, ac0.z); ac0.w = fmaf(e, v0.w, ac0.w);
        ac1.x = fmaf(e, v1.x, ac1.x); ac1.y = fmaf(e, v1.y, ac1.y);
        ac1.z = fmaf(e, v1.z, ac1.z); ac1.w = fmaf(e, v1.w, ac1.w);
        ac2.x = fmaf(e, v2.x, ac2.x); ac2.y = fmaf(e, v2.y, ac2.y);
        ac2.z = fmaf(e, v2.z, ac2.z); ac2.w = fmaf(e, v2.w, ac2.w);
        ac3.x = fmaf(e, v3.x, ac3.x); ac3.y = fmaf(e, v3.y, ac3.y);
        ac3.z = fmaf(e, v3.z, ac3.z); ac3.w = fmaf(e, v3.w, ac3.w);
    }
    float inv = __fdividef(1.f, den);
    float* dst = g_attn + (bb * 64 + qt) * ND + h * 16;
    float4 o0 = {ac0.x*inv, ac0.y*inv, ac0.z*inv, ac0.w*inv};
    float4 o1 = {ac1.x*inv, ac1.y*inv, ac1.z*inv, ac1.w*inv};
    float4 o2 = {ac2.x*inv, ac2.y*inv, ac2.z*inv, ac2.w*inv};
    float4 o3 = {ac3.x*inv, ac3.y*inv, ac3.z*inv, ac3.w*inv};
    *(float4*)(dst)      = o0;
    *(float4*)(dst + 4)  = o1;
    *(float4*)(dst + 8)  = o2;
    *(float4*)(dst + 12) = o3;
}

// ---------------------------------------------------------------------------
// X3: outproj + LN2 + FFN (smem broadcast matvecs) + heads, fused
// ---------------------------------------------------------------------------
__global__ __launch_bounds__(256) void post_heads_kernel(
    const float* __restrict__ out_w, const float* __restrict__ out_b,
    const float* __restrict__ ln2_g, const float* __restrict__ ln2_b,
    const float* __restrict__ w1,    const float* __restrict__ b1,
    const float* __restrict__ w2,    const float* __restrict__ b2,
    const float* __restrict__ gate_w, const float* __restrict__ gate_b,
    const float* __restrict__ row_w,  const float* __restrict__ row_b,
    const float* __restrict__ col_w,  const float* __restrict__ col_b,
    const float* __restrict__ drow_w, const float* __restrict__ drow_b,
    const float* __restrict__ dcol_w, const float* __restrict__ dcol_b,
    const float* __restrict__ delta_scale)
{
    __shared__ float woT[32 * 33];
    __shared__ float w1T[32 * 65];
    __shared__ float w2T[64 * 33];
    __shared__ float sob[32], sb1[64], sb2[32], sgw[32];
    __shared__ __align__(16) float sao[8 * 32];
    __shared__ __align__(16) float sx[8 * 32];
    __shared__ __align__(16) float sh[8 * 64];
    __shared__ __align__(16) float sfeat[8 * 32];

    const int tid  = threadIdx.x;
    const int lane = tid & 31;
    const int wtok = tid >> 5;
    const int token = blockIdx.x * 8 + wtok;

    for (int i = tid; i < 32 * 32; i += 256) {
        int j = i >> 5, k = i & 31;
        woT[k * 33 + j] = __ldg(&out_w[i]);
    }
    for (int i = tid; i < 64 * 32; i += 256) {
        int j = i >> 5, k = i & 31;
        w1T[k * 65 + j] = __ldg(&w1[i]);
    }
    for (int i = tid; i < 32 * 64; i += 256) {
        int d = i >> 6, k = i & 63;
        w2T[k * 33 + d] = __ldg(&w2[i]);
    }
    if (tid < 32) {
        sob[tid] = __ldg(&out_b[tid]);
        sb2[tid] = __ldg(&b2[tid]);
        sgw[tid] = __ldg(&gate_w[tid]);
    }
    if (tid < 64) sb1[tid] = __ldg(&b1[tid]);

    float f = g_feat[token * ND + lane];
    sao[wtok * 32 + lane] = g_attn[token * ND + lane];
    __syncthreads();

    // out proj + residual (broadcast float4 LDS)
    {
        float s = sob[lane];
        const float4* av = (const float4*)(sao + wtok * 32);
#pragma unroll
        for (int k4 = 0; k4 < 8; k4++) {
            float4 xa = av[k4];
            int k = k4 * 4;
            s = fmaf(xa.x, woT[(k+0)*33+lane], s);
            s = fmaf(xa.y, woT[(k+1)*33+lane], s);
            s = fmaf(xa.z, woT[(k+2)*33+lane], s);
            s = fmaf(xa.w, woT[(k+3)*33+lane], s);
        }
        f += s;
    }

    // LN2 (warp butterflies)
    {
        float m = f;
#pragma unroll
        for (int o = 16; o; o >>= 1) m += __shfl_xor_sync(FULL, m, o);
        m *= (1.f / ND);
        float d = f - m;
        float v = d * d;
#pragma unroll
        for (int o = 16; o; o >>= 1) v += __shfl_xor_sync(FULL, v, o);
        float r = rsqrtf(v * (1.f / ND) + 1e-5f);
        sx[wtok * 32 + lane] = d * r * __ldg(&ln2_g[lane]) + __ldg(&ln2_b[lane]);
    }
    __syncwarp();

    // FFN1 + exact GELU: 2 outputs per thread
    {
        float y0 = sb1[lane], y1 = sb1[lane + 32];
        const float4* xv = (const float4*)(sx + wtok * 32);
#pragma unroll
        for (int k4 = 0; k4 < 8; k4++) {
            float4 xa = xv[k4];
            int k = k4 * 4;
            y0 = fmaf(xa.x, w1T[(k+0)*65+lane],    y0);
            y0 = fmaf(xa.y, w1T[(k+1)*65+lane],    y0);
            y0 = fmaf(xa.z, w1T[(k+2)*65+lane],    y0);
            y0 = fmaf(xa.w, w1T[(k+3)*65+lane],    y0);
            y1 = fmaf(xa.x, w1T[(k+0)*65+lane+32], y1);
            y1 = fmaf(xa.y, w1T[(k+1)*65+lane+32], y1);
            y1 = fmaf(xa.z, w1T[(k+2)*65+lane+32], y1);
            y1 = fmaf(xa.w, w1T[(k+3)*65+lane+32], y1);
        }
        sh[wtok * 64 + lane]      = 0.5f * y0 * (1.f + erff(y0 * 0.70710678118654752f));
        sh[wtok * 64 + 32 + lane] = 0.5f * y1 * (1.f + erff(y1 * 0.70710678118654752f));
    }
    __syncwarp();

    // FFN2 + residual
    {
        float s = sb2[lane];
        const float4* hv = (const float4*)(sh + wtok * 64);
#pragma unroll
        for (int k4 = 0; k4 < 16; k4++) {
            float4 xa = hv[k4];
            int k = k4 * 4;
            s = fmaf(xa.x, w2T[(k+0)*33+lane], s);
            s = fmaf(xa.y, w2T[(k+1)*33+lane], s);
            s = fmaf(xa.z, w2T[(k+2)*33+lane], s);
            s = fmaf(xa.w, w2T[(k+3)*33+lane], s);
        }
        f += s;
        sfeat[wtok * 32 + lane] = f;
    }
    __syncthreads();

    // heads: thread = (grp, j); weights in registers, feat broadcast from smem
    {
        const int grp = tid >> 6, j = tid & 63;
        const float* W = (grp == 0) ? row_w : (grp == 1) ? col_w
                       : (grp == 2) ? drow_w : dcol_w;
        const float* Bv = (grp == 0) ? row_b : (grp == 1) ? col_b
                        : (grp == 2) ? drow_b : dcol_b;
        float4 wreg[8];
        const float4* wv = (const float4*)(W + j * 32);
#pragma unroll
        for (int i = 0; i < 8; i++) wreg[i] = __ldg(&wv[i]);
        const float bias = __ldg(&Bv[j]);
        const float gb = __ldg(&gate_b[0]);
        const float ds = __ldg(&delta_scale[0]);
        const int p0 = blockIdx.x * 8;

#pragma unroll
        for (int i = 0; i < 8; i++) {
            const float4* fv = (const float4*)(sfeat + i * 32);
            float s = bias, g = gb;
#pragma unroll
            for (int k4 = 0; k4 < 8; k4++) {
                float4 fa = fv[k4];
                s = fmaf(fa.x, wreg[k4].x, s);
                s = fmaf(fa.y, wreg[k4].y, s);
                s = fmaf(fa.z, wreg[k4].z, s);
                s = fmaf(fa.w, wreg[k4].w, s);
                if (grp == 0) {
                    int k = k4 * 4;
                    g = fmaf(fa.x, sgw[k+0], g);
                    g = fmaf(fa.y, sgw[k+1], g);
                    g = fmaf(fa.z, sgw[k+2], g);
                    g = fmaf(fa.w, sgw[k+3], g);
                }
            }
            int off; float val;
            if (grp == 0)      { off = j;        val = s + g;  }
            else if (grp == 1) { off = 128 + j;  val = s;      }
            else if (grp == 2) { off = 64 + j;   val = s * ds; }
            else               { off = 192 + j;  val = s;      }
            g_heads[(p0 + i) * 256 + off] = val;
        }
    }
}

// ---------------------------------------------------------------------------
// merge — pure stream, reversed order for L2 reuse
// ---------------------------------------------------------------------------
__global__ __launch_bounds__(256) void merge_kernel(
    const float* __restrict__ a, const float* __restrict__ b,
    float* __restrict__ out)
{
    const int chunk = gridDim.x - 1 - blockIdx.x;
    const int gid = chunk * 256 + threadIdx.x;
    const int p  = gid >> 10;
    const int r  = gid & 1023;
    const int h  = r >> 4;
    const int w0 = r & 15;

    const float* hp = g_heads + p * 256;
    const float rg = __ldg(hp + h);
    const float dr = __ldg(hp + 64 + h);
    const float4 cv = __ldg((const float4*)(hp + 128) + w0);
    const float4 dc = __ldg((const float4*)(hp + 192) + w0);

    const float4 av = __ldcs((const float4*)a + gid);
    const float4 bv = __ldcs((const float4*)b + gid);

    float4 ov;
#define MERGE1(comp, cvc, dcc)                                          \
    { float lgt = rg + cvc;                                              \
      float m = __fdividef(1.f, 1.f + __expf(-lgt));                     \
      ov.comp = fmaf(m, av.comp - bv.comp, fmaf(dr, dcc, bv.comp)); }
    MERGE1(x, cv.x, dc.x); MERGE1(y, cv.y, dc.y);
    MERGE1(z, cv.z, dc.z); MERGE1(w, cv.w, dc.w);
#undef MERGE1
    __stcs((float4*)out + gid, ov);
}

// ---------------------------------------------------------------------------
extern "C" void kernel_launch(void* const* d_in, const int* in_sizes, int n_in,
                              void* d_out, int out_size)
{
    const float* a          = (const float*)d_in[0];
    const float* b          = (const float*)d_in[1];
    const float* layer_emb  = (const float*)d_in[2];
    const float* in_proj_w  = (const float*)d_in[3];
    const float* in_proj_b  = (const float*)d_in[4];
    const float* ln1_g      = (const float*)d_in[5];
    const float* ln1_b      = (const float*)d_in[6];
    const float* qkv_w      = (const float*)d_in[7];
    const float* qkv_b      = (const float*)d_in[8];
    const float* out_w      = (const float*)d_in[9];
    const float* out_b      = (const float*)d_in[10];
    const float* ln2_g      = (const float*)d_in[11];
    const float* ln2_b      = (const float*)d_in[12];
    const float* ffn_w1     = (const float*)d_in[13];
    const float* ffn_b1     = (const float*)d_in[14];
    const float* ffn_w2     = (const float*)d_in[15];
    const float* ffn_b2     = (const float*)d_in[16];
    const float* gate_w     = (const float*)d_in[17];
    const float* gate_b     = (const float*)d_in[18];
    const float* row_w      = (const float*)d_in[19];
    const float* row_b      = (const float*)d_in[20];
    const float* col_w      = (const float*)d_in[21];
    const float* col_b      = (const float*)d_in[22];
    const float* drow_w     = (const float*)d_in[23];
    const float* drow_b     = (const float*)d_in[24];
    const float* dcol_w     = (const float*)d_in[25];
    const float* dcol_b     = (const float*)d_in[26];
    const float* dscale     = (const float*)d_in[27];
    float* out              = (float*)d_out;

    stats_kernel<<<NP, 256>>>(a, b, layer_emb, in_proj_w, in_proj_b);
    ln1_qkv_kernel<<<NP / 8, 256>>>(ln1_g, ln1_b, qkv_w, qkv_b);
    attn_kernel<<<NB * 2, 64>>>();
    post_heads_kernel<<<NP / 8, 256>>>(out_w, out_b, ln2_g, ln2_b,
                                       ffn_w1, ffn_b1, ffn_w2, ffn_b2,
                                       gate_w, gate_b, row_w, row_b,
                                       col_w, col_b, drow_w, drow_b,
                                       dcol_w, dcol_b, dscale);
    merge_kernel<<<NP * PIX / 4 / 256, 256>>>(a, b, out);
}